// round 8
// baseline (speedup 1.0000x reference)
#include <cuda_runtime.h>
#include <cuda_bf16.h>
#include <cstdint>

// Problem constants
#define BB 8
#define NN 256
#define BN 2048          // BB*NN
#define EE 16384
#define HH 256
#define NHD 8
#define HD 32
#define VD 8

typedef __nv_bfloat16 bf16;

// ---------------- fp32 scratch ------------------------------------------------
__device__ float g_q   [BN*HH];
__device__ float g_k   [BN*HH];
__device__ float g_vv  [BN*HH];
__device__ float g_v   [BN*HH];
__device__ float g_vp  [BN*VD*2*HH];
__device__ float g_s12 [EE*2*HH];
__device__ float g_o   [BN*3*HH];
__device__ float g_T   [BN*VD*HH];
__device__ float g_S   [BN*VD*HH];
__device__ float g_ff  [EE*HH];
__device__ float g_zb  [3*HH];          // zero bias (static zero-init)

// ---------------- bf16 hi/lo scratch -----------------------------------------
__device__ bf16 g_xnh [BN*HH],    g_xnl [BN*HH];
__device__ bf16 g_vath[BN*HH],    g_vatl[BN*HH];
__device__ bf16 g_fijh[EE*HH],    g_fijl[EE*HH];
__device__ bf16 g_vjh [EE*HH],    g_vjl [EE*HH];
__device__ bf16 g_vech[BN*VD*HH], g_vecl[BN*VD*HH];
__device__ bf16 g_xagh[BN*HH],    g_xagl[BN*HH];
#define WROWS 3840
__device__ bf16 g_wh[WROWS*HH], g_wl[WROWS*HH];

// ---------------- CSR scratch -------------------------------------------------
__device__ int g_rowstart[BN + 1];
__device__ int g_elist[EE];

// weight row offsets within g_wh/g_wl
#define OFF_WQ   0
#define OFF_WK   256
#define OFF_WV   512
#define OFF_WAO  768
#define OFF_WDV  1024
#define OFF_WF   1280
#define OFF_WS   1536
#define OFF_WVEC 2048
#define OFF_WO   2560
#define OFF_WTRG 3328
#define OFF_WSRC 3584

__device__ __forceinline__ float silu_f(float x) { return x / (1.f + __expf(-x)); }
__device__ __forceinline__ float cut_f(float rr) {
    return (rr < 5.f) ? 0.5f * (cosf(rr * 0.6283185307179586f) + 1.f) : 0.f;
}

__device__ __forceinline__ uint32_t smem_u32(const void* p) {
    uint32_t a;
    asm("{ .reg .u64 t; cvta.to.shared.u64 t, %1; cvt.u32.u64 %0, t; }" : "=r"(a) : "l"(p));
    return a;
}

// ---------------- mma.sync / ldmatrix / cp.async wrappers --------------------
__device__ __forceinline__ void ldsm4(uint32_t* r, uint32_t addr) {
    asm volatile("ldmatrix.sync.aligned.m8n8.x4.shared.b16 {%0,%1,%2,%3}, [%4];"
                 : "=r"(r[0]), "=r"(r[1]), "=r"(r[2]), "=r"(r[3]) : "r"(addr));
}
__device__ __forceinline__ void mma_bf16(float* d, const uint32_t* a, const uint32_t* b) {
    asm volatile("mma.sync.aligned.m16n8k16.row.col.f32.bf16.bf16.f32 "
                 "{%0,%1,%2,%3}, {%4,%5,%6,%7}, {%8,%9}, {%0,%1,%2,%3};"
                 : "+f"(d[0]), "+f"(d[1]), "+f"(d[2]), "+f"(d[3])
                 : "r"(a[0]), "r"(a[1]), "r"(a[2]), "r"(a[3]), "r"(b[0]), "r"(b[1]));
}
#define CP_COMMIT() asm volatile("cp.async.commit_group;" ::: "memory")

// =============================================================================
// Unified job-table GEMM, 128x64 tiles (96KB smem -> 2 CTAs/SM).
// Mode 0: C = [silu](A@W^T + bias) fp32.
// Mode 1: vj epilogue silu(acc+bias)*cut(r[row])*v[src[row]][col] -> bf16 hi/lo.
// =============================================================================
struct GJob {
    const bf16 *Ah, *Al, *Bh, *Bl;
    const float* bias;
    float* C;
    int Nfull, colTiles, silu, tileOfs;
};
struct GArgs {
    GJob jobs[7];
    int njobs;
    int mode;
    const float* vsrc; const int* srcidx; const float* rij;
    bf16 *Oh, *Ol;
};

#define CHUNK_BYTES 49152
#define MG_SMEM (2 * CHUNK_BYTES)   // 96 KB

__device__ __forceinline__ void cp_tileA(uint32_t dst_s, const bf16* __restrict__ src,
                                         int rowbase, int kc, int tid)
{
    const char* g = (const char*)(src + (size_t)rowbase * HH + kc * 64);
#pragma unroll
    for (int it = 0; it < 4; it++) {
        int u   = tid + it * 256;       // 1024 units: 128 rows x 8
        int row = u >> 3;
        int ui  = u & 7;
        uint32_t off = row * 128 + ui * 16;
        off ^= (off >> 3) & 0x70;
        asm volatile("cp.async.cg.shared.global [%0], [%1], 16;"
                     :: "r"(dst_s + off), "l"(g + (size_t)row * 512 + ui * 16));
    }
}
__device__ __forceinline__ void cp_tileB(uint32_t dst_s, const bf16* __restrict__ src,
                                         int rowbase, int kc, int tid)
{
    const char* g = (const char*)(src + (size_t)rowbase * HH + kc * 64);
#pragma unroll
    for (int it = 0; it < 2; it++) {
        int u   = tid + it * 256;       // 512 units: 64 rows x 8
        int row = u >> 3;
        int ui  = u & 7;
        uint32_t off = row * 128 + ui * 16;
        off ^= (off >> 3) & 0x70;
        asm volatile("cp.async.cg.shared.global [%0], [%1], 16;"
                     :: "r"(dst_s + off), "l"(g + (size_t)row * 512 + ui * 16));
    }
}

__device__ __forceinline__ void cp_chunk(uint32_t sbase,
    const bf16* Ah, const bf16* Al, const bf16* Bh, const bf16* Bl,
    int rowA, int colB, int kc, int tid)
{
    cp_tileA(sbase,         Ah, rowA, kc, tid);
    cp_tileA(sbase + 16384, Al, rowA, kc, tid);
    cp_tileB(sbase + 32768, Bh, colB, kc, tid);
    cp_tileB(sbase + 40960, Bl, colB, kc, tid);
}

__global__ __launch_bounds__(256) void gemm_kernel(GArgs P)
{
    extern __shared__ uint8_t smem[];
    const int tid = threadIdx.x, wid = tid >> 5, lane = tid & 31;

    int j = 0;
#pragma unroll
    for (int jj = 1; jj < 7; jj++)
        if (jj < P.njobs && (int)blockIdx.x >= P.jobs[jj].tileOfs) j = jj;
    const GJob job = P.jobs[j];
    const int local = blockIdx.x - job.tileOfs;
    const int rowA = (local / job.colTiles) * 128;
    const int colB = (local % job.colTiles) * 64;

    const bf16* __restrict__ Ah = job.Ah;
    const bf16* __restrict__ Al = job.Al;
    const bf16* __restrict__ Bh = job.Bh;
    const bf16* __restrict__ Bl = job.Bl;

    const int wr = wid >> 1, wc = wid & 1;   // warp tile: 32 rows x 32 cols

    uint32_t aoff[2], boff[2];
#pragma unroll
    for (int i = 0; i < 2; i++)
        aoff[i] = (uint32_t)((wr * 32 + i * 16 + (lane & 15)) * 128 + (lane >> 4) * 16);
    {
        int grp = lane >> 3, lr = lane & 7;
#pragma unroll
        for (int j2 = 0; j2 < 2; j2++)
            boff[j2] = (uint32_t)((wc * 32 + j2 * 16 + (grp >> 1) * 8 + lr) * 128
                                  + (grp & 1) * 16);
    }

    const uint32_t sb = smem_u32(smem);

    float acc[2][4][4];
#pragma unroll
    for (int i = 0; i < 2; i++)
#pragma unroll
        for (int jj = 0; jj < 4; jj++)
#pragma unroll
            for (int r = 0; r < 4; r++) acc[i][jj][r] = 0.f;

    cp_chunk(sb,               Ah, Al, Bh, Bl, rowA, colB, 0, tid); CP_COMMIT();
    cp_chunk(sb + CHUNK_BYTES, Ah, Al, Bh, Bl, rowA, colB, 1, tid); CP_COMMIT();

    int buf = 0;
    for (int kc = 0; kc < 4; kc++) {
        if (kc < 3) asm volatile("cp.async.wait_group 1;" ::: "memory");
        else        asm volatile("cp.async.wait_group 0;" ::: "memory");
        __syncthreads();
        const uint32_t base = sb + buf * CHUNK_BYTES;
#pragma unroll
        for (int ks = 0; ks < 4; ks++) {
            const uint32_t kb = ks * 32;
            uint32_t ahf[2][4], alf[2][4], bhf[2][4], blf[2][4];
#pragma unroll
            for (int i = 0; i < 2; i++) {
                uint32_t o = aoff[i] + kb; o ^= (o >> 3) & 0x70;
                ldsm4(ahf[i], base + o);
                ldsm4(alf[i], base + 16384 + o);
            }
#pragma unroll
            for (int j2 = 0; j2 < 2; j2++) {
                uint32_t o = boff[j2] + kb; o ^= (o >> 3) & 0x70;
                ldsm4(bhf[j2], base + 32768 + o);
                ldsm4(blf[j2], base + 40960 + o);
            }
#pragma unroll
            for (int i = 0; i < 2; i++)
#pragma unroll
                for (int jj = 0; jj < 4; jj++) {
                    const uint32_t* b_hi = &bhf[jj >> 1][(jj & 1) * 2];
                    const uint32_t* b_lo = &blf[jj >> 1][(jj & 1) * 2];
                    mma_bf16(acc[i][jj], ahf[i], b_hi);
                    mma_bf16(acc[i][jj], ahf[i], b_lo);
                    mma_bf16(acc[i][jj], alf[i], b_hi);
                }
        }
        __syncthreads();
        if (kc + 2 <= 3) {
            cp_chunk(sb + buf * CHUNK_BYTES, Ah, Al, Bh, Bl, rowA, colB, kc + 2, tid);
            CP_COMMIT();
        }
        buf ^= 1;
    }

    const float* bias = job.bias;
    const int r0 = lane >> 2, c0 = (lane & 3) * 2;

    if (P.mode == 1) {
        __nv_bfloat162* OH = (__nv_bfloat162*)P.Oh;
        __nv_bfloat162* OL = (__nv_bfloat162*)P.Ol;
#pragma unroll
        for (int i = 0; i < 2; i++) {
            const int row0 = rowA + wr * 32 + i * 16 + r0;
            const int row1 = row0 + 8;
            const int s0 = P.srcidx[row0], s1i = P.srcidx[row1];
            const float cut0 = cut_f(P.rij[row0]);
            const float cut1 = cut_f(P.rij[row1]);
#pragma unroll
            for (int jj = 0; jj < 4; jj++) {
                const int gcol = colB + wc * 32 + jj * 8 + c0;
                const float b0 = bias[gcol], b1 = bias[gcol + 1];
                float v0 = silu_f(acc[i][jj][0] + b0) * cut0 * P.vsrc[(size_t)s0 * HH + gcol];
                float v1 = silu_f(acc[i][jj][1] + b1) * cut0 * P.vsrc[(size_t)s0 * HH + gcol + 1];
                float v2 = silu_f(acc[i][jj][2] + b0) * cut1 * P.vsrc[(size_t)s1i * HH + gcol];
                float v3 = silu_f(acc[i][jj][3] + b1) * cut1 * P.vsrc[(size_t)s1i * HH + gcol + 1];
                bf16 h0 = __float2bfloat16(v0), h1 = __float2bfloat16(v1);
                bf16 h2 = __float2bfloat16(v2), h3 = __float2bfloat16(v3);
                bf16 l0 = __float2bfloat16(v0 - __bfloat162float(h0));
                bf16 l1 = __float2bfloat16(v1 - __bfloat162float(h1));
                bf16 l2 = __float2bfloat16(v2 - __bfloat162float(h2));
                bf16 l3 = __float2bfloat16(v3 - __bfloat162float(h3));
                OH[(size_t)row0 * 128 + (gcol >> 1)] = __nv_bfloat162(h0, h1);
                OL[(size_t)row0 * 128 + (gcol >> 1)] = __nv_bfloat162(l0, l1);
                OH[(size_t)row1 * 128 + (gcol >> 1)] = __nv_bfloat162(h2, h3);
                OL[(size_t)row1 * 128 + (gcol >> 1)] = __nv_bfloat162(l2, l3);
            }
        }
    } else {
        float* __restrict__ C = job.C;
        const int Nfull = job.Nfull;
        const int do_silu = job.silu;
#pragma unroll
        for (int i = 0; i < 2; i++) {
            const int grow = rowA + wr * 32 + i * 16 + r0;
#pragma unroll
            for (int jj = 0; jj < 4; jj++) {
                const int gcol = colB + wc * 32 + jj * 8 + c0;
                float b0 = bias[gcol], b1 = bias[gcol + 1];
                float v0 = acc[i][jj][0] + b0, v1 = acc[i][jj][1] + b1;
                float v2 = acc[i][jj][2] + b0, v3 = acc[i][jj][3] + b1;
                if (do_silu) {
                    v0 = silu_f(v0); v1 = silu_f(v1); v2 = silu_f(v2); v3 = silu_f(v3);
                }
                *(float2*)(C + (size_t)grow * Nfull + gcol)       = make_float2(v0, v1);
                *(float2*)(C + (size_t)(grow + 8) * Nfull + gcol) = make_float2(v2, v3);
            }
        }
    }
}

// =============================================================================
// prep_kernel: wprep (8448) | conv fij (4096) | conv vec (4096) | ln (2048) | CSR (1)
// =============================================================================
struct PrepArgs {
    const float* wsrc[11]; int wN[11]; int woff[11];
    const float* f_ij; const float* vec; const float* x;
    const float* ln_w; const float* ln_b; const int* dst;
};

__device__ __forceinline__ void conv_body(int i, const float* __restrict__ in,
                                          bf16* hi, bf16* lo)
{
    float4 v = ((const float4*)in)[i];
    bf16 h0 = __float2bfloat16(v.x), h1 = __float2bfloat16(v.y);
    bf16 h2 = __float2bfloat16(v.z), h3 = __float2bfloat16(v.w);
    bf16 l0 = __float2bfloat16(v.x - __bfloat162float(h0));
    bf16 l1 = __float2bfloat16(v.y - __bfloat162float(h1));
    bf16 l2 = __float2bfloat16(v.z - __bfloat162float(h2));
    bf16 l3 = __float2bfloat16(v.w - __bfloat162float(h3));
    __nv_bfloat162* hp = (__nv_bfloat162*)hi;
    __nv_bfloat162* lp = (__nv_bfloat162*)lo;
    hp[2 * i]     = __nv_bfloat162(h0, h1);
    hp[2 * i + 1] = __nv_bfloat162(h2, h3);
    lp[2 * i]     = __nv_bfloat162(l0, l1);
    lp[2 * i + 1] = __nv_bfloat162(l2, l3);
}

#define PREP_WP   8448
#define PREP_CF   4096
#define PREP_CV   4096
#define PREP_LN   2048
#define PREP_TOT  (PREP_WP + PREP_CF + PREP_CV + PREP_LN + 1)

__global__ __launch_bounds__(256) void prep_kernel(PrepArgs P)
{
    __shared__ int csr_s[BN];
    __shared__ float red[8];
    int bx = blockIdx.x;
    const int t = threadIdx.x;

    if (bx < PREP_WP) {               // weight prep
        int w = bx / 768, n = bx % 768;
        if (n < P.wN[w]) {
            float v = P.wsrc[w][(size_t)t * P.wN[w] + n];
            bf16 h = __float2bfloat16(v);
            bf16 l = __float2bfloat16(v - __bfloat162float(h));
            size_t o = (size_t)(P.woff[w] + n) * HH + t;
            g_wh[o] = h; g_wl[o] = l;
        }
        return;
    }
    bx -= PREP_WP;
    if (bx < PREP_CF) { conv_body(bx * 256 + t, P.f_ij, g_fijh, g_fijl); return; }
    bx -= PREP_CF;
    if (bx < PREP_CV) { conv_body(bx * 256 + t, P.vec, g_vech, g_vecl); return; }
    bx -= PREP_CV;
    if (bx < PREP_LN) {               // LayerNorm
        int n = bx;
        float v = P.x[n * HH + t];
        float s = v;
#pragma unroll
        for (int o = 16; o; o >>= 1) s += __shfl_xor_sync(0xffffffffu, s, o);
        if ((t & 31) == 0) red[t >> 5] = s;
        __syncthreads();
        float tot = 0.f;
#pragma unroll
        for (int i = 0; i < 8; i++) tot += red[i];
        float mu = tot * (1.f / HH);
        float dv = v - mu;
        float s2 = dv * dv;
#pragma unroll
        for (int o = 16; o; o >>= 1) s2 += __shfl_xor_sync(0xffffffffu, s2, o);
        __syncthreads();
        if ((t & 31) == 0) red[t >> 5] = s2;
        __syncthreads();
        float var = 0.f;
#pragma unroll
        for (int i = 0; i < 8; i++) var += red[i];
        var *= (1.f / HH);
        float xn = dv * rsqrtf(var + 1e-5f) * P.ln_w[t] + P.ln_b[t];
        bf16 hh2 = __float2bfloat16(xn);
        g_xnh[n * HH + t] = hh2;
        g_xnl[n * HH + t] = __float2bfloat16(xn - __bfloat162float(hh2));
        return;
    }

    // ---- CSR build (single block) ----
    for (int i = t; i < BN; i += 256) csr_s[i] = 0;
    __syncthreads();
    const int4* d4 = (const int4*)P.dst;
#pragma unroll
    for (int i = 0; i < 16; i++) {
        int4 v = d4[t * 16 + i];
        atomicAdd(&csr_s[v.x], 1); atomicAdd(&csr_s[v.y], 1);
        atomicAdd(&csr_s[v.z], 1); atomicAdd(&csr_s[v.w], 1);
    }
    __syncthreads();
    for (int d = 1; d < BN; d <<= 1) {
        for (int i = t; i < BN / (2 * d); i += 256) {
            int idx = (i + 1) * 2 * d - 1;
            csr_s[idx] += csr_s[idx - d];
        }
        __syncthreads();
    }
    if (t == 0) { g_rowstart[BN] = csr_s[BN - 1]; csr_s[BN - 1] = 0; }
    __syncthreads();
    for (int d = BN / 2; d >= 1; d >>= 1) {
        for (int i = t; i < BN / (2 * d); i += 256) {
            int idx = (i + 1) * 2 * d - 1;
            int a = csr_s[idx - d];
            csr_s[idx - d] = csr_s[idx];
            csr_s[idx] += a;
        }
        __syncthreads();
    }
    for (int i = t; i < BN; i += 256) g_rowstart[i] = csr_s[i];
    __syncthreads();
#pragma unroll
    for (int i = 0; i < 16; i++) {
        int4 v = d4[t * 16 + i];
        int e = t * 64 + i * 4;
        int p0 = atomicAdd(&csr_s[v.x], 1); g_elist[p0] = e;
        int p1 = atomicAdd(&csr_s[v.y], 1); g_elist[p1] = e + 1;
        int p2 = atomicAdd(&csr_s[v.z], 1); g_elist[p2] = e + 2;
        int p3 = atomicAdd(&csr_s[v.w], 1); g_elist[p3] = e + 3;
    }
}

// =============================================================================
// attention (64 blocks)
// =============================================================================
__global__ __launch_bounds__(256) void attn_kernel()
{
    __shared__ float ks[64][32];
    __shared__ float vs[64][32];
    int b = blockIdx.x >> 3;
    int hd = blockIdx.x & 7;
    int i = threadIdx.x;
    float qr[32];
    const float* qrow = g_q + (size_t)(b * NN + i) * HH + hd * HD;
#pragma unroll
    for (int d = 0; d < 32; d++) qr[d] = qrow[d];
    float acc[32];
#pragma unroll
    for (int d = 0; d < 32; d++) acc[d] = 0.f;
    const float scale = rsqrtf((float)HD);

    for (int j0 = 0; j0 < NN; j0 += 64) {
        __syncthreads();
        for (int l = threadIdx.x; l < 512; l += 256) {
            int jr = l >> 3;
            int dc = (l & 7) * 4;
            size_t base = (size_t)(b * NN + j0 + jr) * HH + hd * HD + dc;
            *(float4*)&ks[jr][dc] = *(const float4*)&g_k[base];
            *(float4*)&vs[jr][dc] = *(const float4*)&g_vv[base];
        }
        __syncthreads();
        for (int j = 0; j < 64; j++) {
            float s = 0.f;
#pragma unroll
            for (int d = 0; d < 32; d++) s += qr[d] * ks[j][d];
            s = silu_f(s * scale);
#pragma unroll
            for (int d = 0; d < 32; d++) acc[d] += s * vs[j][d];
        }
    }
    size_t base = (size_t)(b * NN + i) * HH + hd * HD;
#pragma unroll
    for (int d = 0; d < 32; d++) {
        float val = acc[d] * (1.f / NN);
        bf16 h2 = __float2bfloat16(val);
        g_vath[base + d] = h2;
        g_vatl[base + d] = __float2bfloat16(val - __bfloat162float(h2));
    }
}

// =============================================================================
// wdot (EE blocks)
// =============================================================================
__global__ __launch_bounds__(256) void wdot_kernel(
    const int* __restrict__ src, const int* __restrict__ dst,
    const float* __restrict__ dij, float* __restrict__ df)
{
    __shared__ float dsh[VD];
    int e = blockIdx.x;
    int h = threadIdx.x;
    if (h < VD) dsh[h] = dij[e * VD + h];
    __syncthreads();
    int s = src[e], tt = dst[e];
    float tv[VD], sv[VD];
    float pT = 0.f, pS = 0.f;
#pragma unroll
    for (int vd = 0; vd < VD; vd++) {
        tv[vd] = g_T[(size_t)(tt * VD + vd) * HH + h];
        sv[vd] = g_S[(size_t)(s * VD + vd) * HH + h];
        pT += tv[vd] * dsh[vd];
        pS += sv[vd] * dsh[vd];
    }
    float wd = 0.f;
#pragma unroll
    for (int vd = 0; vd < VD; vd++)
        wd += (tv[vd] - pT * dsh[vd]) * (sv[vd] - pS * dsh[vd]);
    df[(size_t)e * HH + h] = g_ff[(size_t)e * HH + h] * wd;
}

// ======================= gather: x_agg + dvec (no atomics) ===================
__global__ __launch_bounds__(256) void gather_kernel(
    const float* __restrict__ s12, const float* __restrict__ vec,
    const float* __restrict__ dij, const int* __restrict__ src,
    float* __restrict__ dvec_out)
{
    int n = blockIdx.x, h = threadIdx.x;
    int beg = g_rowstart[n], end = g_rowstart[n + 1];
    float xa = 0.f;
    float dv[VD];
#pragma unroll
    for (int vd = 0; vd < VD; vd++) dv[vd] = 0.f;

    for (int i = beg; i < end; i++) {
        int e = g_elist[i];
        int s = src[e];
        float vje = __bfloat162float(g_vjh[(size_t)e * HH + h]) +
                    __bfloat162float(g_vjl[(size_t)e * HH + h]);
        xa += vje;
        float s1  = s12[(size_t)e * (2 * HH) + h];
        float s2v = s12[(size_t)e * (2 * HH) + HH + h];
#pragma unroll
        for (int vd = 0; vd < VD; vd++)
            dv[vd] += vec[(size_t)s * (VD * HH) + vd * HH + h] * s1
                    + s2v * dij[e * VD + vd];
    }
    bf16 hh = __float2bfloat16(xa);
    g_xagh[n * HH + h] = hh;
    g_xagl[n * HH + h] = __float2bfloat16(xa - __bfloat162float(hh));
#pragma unroll
    for (int vd = 0; vd < VD; vd++)
        dvec_out[(size_t)n * (VD * HH) + vd * HH + h] = dv[vd];
}

// ======================= finalize ============================================
__global__ __launch_bounds__(256) void finalize_kernel(float* __restrict__ dx,
                                                       float* __restrict__ dvec)
{
    int n = blockIdx.x, h = threadIdx.x;
    float o1 = g_o[(size_t)n * (3 * HH) + h];
    float o2 = g_o[(size_t)n * (3 * HH) + HH + h];
    float o3 = g_o[(size_t)n * (3 * HH) + 2 * HH + h];
    float vsum = 0.f;
#pragma unroll
    for (int vd = 0; vd < VD; vd++)
        vsum += g_vp[(size_t)(n * VD + vd) * (2 * HH) + h];
    dx[n * HH + h] = vsum * o2 + o3;
#pragma unroll
    for (int vd = 0; vd < VD; vd++) {
        float vec3 = g_vp[(size_t)(n * VD + vd) * (2 * HH) + HH + h];
        dvec[(size_t)n * (VD * HH) + vd * HH + h] += vec3 * o1;
    }
}

// ======================= launcher ============================================
extern "C" void kernel_launch(void* const* d_in, const int* in_sizes, int n_in,
                              void* d_out, int out_size)
{
    const float* x    = (const float*)d_in[0];
    const float* vec  = (const float*)d_in[1];
    const int*   ei   = (const int*)d_in[2];
    const float* r_ij = (const float*)d_in[3];
    const float* f_ij = (const float*)d_in[4];
    const float* d_ij = (const float*)d_in[5];
    const float* ln_w = (const float*)d_in[7];
    const float* ln_b = (const float*)d_in[8];
    const float* Wq   = (const float*)d_in[9];
    const float* Wk   = (const float*)d_in[10];
    const float* Wv   = (const float*)d_in[11];
    const float* Wao  = (const float*)d_in[12];
    const float* Wvec = (const float*)d_in[13];
    const float* Wdv  = (const float*)d_in[14];
    const float* bdv  = (const float*)d_in[15];
    const float* Ws   = (const float*)d_in[16];
    const float* bs   = (const float*)d_in[17];
    const float* Wo   = (const float*)d_in[18];
    const float* bo   = (const float*)d_in[19];
    const float* Wf   = (const float*)d_in[20];
    const float* bf   = (const float*)d_in[21];
    const float* Wsrc = (const float*)d_in[22];
    const float* Wtrg = (const float*)d_in[23];

    const int* src = ei;
    const int* dst = ei + EE;

    float* out      = (float*)d_out;
    float* out_dx   = out;
    float* out_dvec = out + (size_t)BN * HH;
    float* out_df   = out_dvec + (size_t)BN * VD * HH;

    float *p_q, *p_k, *p_vv, *p_v, *p_vp, *p_s12, *p_o, *p_T, *p_S, *p_ff, *p_zb;
    bf16 *p_xnh, *p_xnl, *p_vath, *p_vatl, *p_fijh, *p_fijl, *p_vjh, *p_vjl,
         *p_vech, *p_vecl, *p_xagh, *p_xagl, *p_wh, *p_wl;
    cudaGetSymbolAddress((void**)&p_q,    g_q);
    cudaGetSymbolAddress((void**)&p_k,    g_k);
    cudaGetSymbolAddress((void**)&p_vv,   g_vv);
    cudaGetSymbolAddress((void**)&p_v,    g_v);
    cudaGetSymbolAddress((void**)&p_vp,   g_vp);
    cudaGetSymbolAddress((void**)&p_s12,  g_s12);
    cudaGetSymbolAddress((void**)&p_o,    g_o);
    cudaGetSymbolAddress((void**)&p_T,    g_T);
    cudaGetSymbolAddress((void**)&p_S,    g_S);
    cudaGetSymbolAddress((void**)&p_ff,   g_ff);
    cudaGetSymbolAddress((void**)&p_zb,   g_zb);
    cudaGetSymbolAddress((void**)&p_xnh,  g_xnh);
    cudaGetSymbolAddress((void**)&p_xnl,  g_xnl);
    cudaGetSymbolAddress((void**)&p_vath, g_vath);
    cudaGetSymbolAddress((void**)&p_vatl, g_vatl);
    cudaGetSymbolAddress((void**)&p_fijh, g_fijh);
    cudaGetSymbolAddress((void**)&p_fijl, g_fijl);
    cudaGetSymbolAddress((void**)&p_vjh,  g_vjh);
    cudaGetSymbolAddress((void**)&p_vjl,  g_vjl);
    cudaGetSymbolAddress((void**)&p_vech, g_vech);
    cudaGetSymbolAddress((void**)&p_vecl, g_vecl);
    cudaGetSymbolAddress((void**)&p_xagh, g_xagh);
    cudaGetSymbolAddress((void**)&p_xagl, g_xagl);
    cudaGetSymbolAddress((void**)&p_wh,   g_wh);
    cudaGetSymbolAddress((void**)&p_wl,   g_wl);

    cudaFuncSetAttribute(gemm_kernel, cudaFuncAttributeMaxDynamicSharedMemorySize, MG_SMEM);

    auto WH = [&](int off) { return p_wh + (size_t)off * HH; };
    auto WL = [&](int off) { return p_wl + (size_t)off * HH; };

    // fork/join stream + events (created per call; a handful of calls total)
    cudaStream_t s2;
    cudaStreamCreateWithFlags(&s2, cudaStreamNonBlocking);
    cudaEvent_t evA, evB, evC;
    cudaEventCreateWithFlags(&evA, cudaEventDisableTiming);
    cudaEventCreateWithFlags(&evB, cudaEventDisableTiming);
    cudaEventCreateWithFlags(&evC, cudaEventDisableTiming);

    // ---- 1. prep (wprep + convs + ln + CSR) on stream 0 ----
    {
        PrepArgs P{};
        const float* srcs[11] = {Wq, Wk, Wv, Wao, Wdv, Wf, Ws, Wvec, Wo, Wtrg, Wsrc};
        int ns[11]   = {256, 256, 256, 256, 256, 256, 512, 512, 768, 256, 256};
        int offs[11] = {OFF_WQ, OFF_WK, OFF_WV, OFF_WAO, OFF_WDV, OFF_WF,
                        OFF_WS, OFF_WVEC, OFF_WO, OFF_WTRG, OFF_WSRC};
        for (int i = 0; i < 11; i++) { P.wsrc[i] = srcs[i]; P.wN[i] = ns[i]; P.woff[i] = offs[i]; }
        P.f_ij = f_ij; P.vec = vec; P.x = x; P.ln_w = ln_w; P.ln_b = ln_b; P.dst = dst;
        prep_kernel<<<PREP_TOT, 256>>>(P);
    }

    // ---- fork: stream2 runs the big independent branch ----
    cudaEventRecord(evA, 0);
    cudaStreamWaitEvent(s2, evA, 0);

    // stream2: ff/vp/T/S (4 jobs, 2560 tiles) -> wdot
    {
        GArgs A{};
        A.njobs = 4; A.mode = 0;
        A.jobs[0] = {p_fijh, p_fijl, WH(OFF_WF),   WL(OFF_WF),   bf,   p_ff, HH,     4, 1, 0};
        A.jobs[1] = {p_vech, p_vecl, WH(OFF_WVEC), WL(OFF_WVEC), p_zb, p_vp, 2 * HH, 8, 0, 512};
        A.jobs[2] = {p_vech, p_vecl, WH(OFF_WTRG), WL(OFF_WTRG), p_zb, p_T,  HH,     4, 0, 1536};
        A.jobs[3] = {p_vech, p_vecl, WH(OFF_WSRC), WL(OFF_WSRC), p_zb, p_S,  HH,     4, 0, 2048};
        gemm_kernel<<<2560, 256, MG_SMEM, s2>>>(A);
    }
    cudaEventRecord(evB, s2);                       // ff/vp/T/S ready
    wdot_kernel<<<EE, 256, 0, s2>>>(src, dst, d_ij, out_df);
    cudaEventRecord(evC, s2);                       // branch done

    // ---- stream0 critical chain ----
    // qkv (3 jobs, 192 tiles)
    {
        GArgs A{};
        A.njobs = 3; A.mode = 0;
        A.jobs[0] = {p_xnh, p_xnl, WH(OFF_WQ), WL(OFF_WQ), p_zb, p_q,  HH, 4, 0, 0};
        A.jobs[1] = {p_xnh, p_xnl, WH(OFF_WK), WL(OFF_WK), p_zb, p_k,  HH, 4, 0, 64};
        A.jobs[2] = {p_xnh, p_xnl, WH(OFF_WV), WL(OFF_WV), p_zb, p_vv, HH, 4, 0, 128};
        gemm_kernel<<<192, 256, MG_SMEM>>>(A);
    }

    // attention
    attn_kernel<<<64, 256>>>();

    // v = vatt @ Wao (64 tiles)
    {
        GArgs A{};
        A.njobs = 1; A.mode = 0;
        A.jobs[0] = {p_vath, p_vatl, WH(OFF_WAO), WL(OFF_WAO), p_zb, p_v, HH, 4, 0, 0};
        gemm_kernel<<<64, 256, MG_SMEM>>>(A);
    }

    // vj = silu(f_ij @ Wdv + bdv)*cut*v[src] -> bf16 hi/lo (512 tiles)
    {
        GArgs A{};
        A.njobs = 1; A.mode = 1;
        A.jobs[0] = {p_fijh, p_fijl, WH(OFF_WDV), WL(OFF_WDV), bdv, nullptr, HH, 4, 0, 0};
        A.vsrc = p_v; A.srcidx = src; A.rij = r_ij; A.Oh = p_vjh; A.Ol = p_vjl;
        gemm_kernel<<<512, 256, MG_SMEM>>>(A);
    }

    // s12 = silu(v_j @ Ws + bs) (1024 tiles)
    {
        GArgs A{};
        A.njobs = 1; A.mode = 0;
        A.jobs[0] = {p_vjh, p_vjl, WH(OFF_WS), WL(OFF_WS), bs, p_s12, 2 * HH, 8, 1, 0};
        gemm_kernel<<<1024, 256, MG_SMEM>>>(A);
    }

    // gather
    gather_kernel<<<BN, 256>>>(p_s12, vec, d_ij, src, out_dvec);

    // o = x_agg @ Wo + bo (192 tiles)
    {
        GArgs A{};
        A.njobs = 1; A.mode = 0;
        A.jobs[0] = {p_xagh, p_xagl, WH(OFF_WO), WL(OFF_WO), bo, p_o, 3 * HH, 12, 0, 0};
        gemm_kernel<<<192, 256, MG_SMEM>>>(A);
    }

    // finalize needs vp from stream2 branch
    cudaStreamWaitEvent(0, evB, 0);
    finalize_kernel<<<BN, 256>>>(out_dx, out_dvec);

    // join branch (wdot) before returning
    cudaStreamWaitEvent(0, evC, 0);
}

// round 9
// speedup vs baseline: 1.0425x; 1.0425x over previous
#include <cuda_runtime.h>
#include <cuda_bf16.h>
#include <cstdint>

// Problem constants
#define BB 8
#define NN 256
#define BN 2048          // BB*NN
#define EE 16384
#define HH 256
#define NHD 8
#define HD 32
#define VD 8

typedef __nv_bfloat16 bf16;

// ---------------- fp32 scratch ------------------------------------------------
__device__ float g_q   [BN*HH];
__device__ float g_k   [BN*HH];
__device__ float g_vv  [BN*HH];
__device__ float g_v   [BN*HH];
__device__ float g_vp  [BN*VD*2*HH];
__device__ float g_s12 [EE*2*HH];
__device__ float g_o   [BN*3*HH];
__device__ float g_T   [BN*VD*HH];
__device__ float g_S   [BN*VD*HH];
__device__ float g_ff  [EE*HH];
__device__ float g_zb  [3*HH];          // zero bias (static zero-init)

// ---------------- bf16 hi/lo scratch -----------------------------------------
__device__ bf16 g_xnh [BN*HH],    g_xnl [BN*HH];
__device__ bf16 g_vath[BN*HH],    g_vatl[BN*HH];
__device__ bf16 g_fijh[EE*HH],    g_fijl[EE*HH];
__device__ bf16 g_vjh [EE*HH],    g_vjl [EE*HH];
__device__ bf16 g_vech[BN*VD*HH], g_vecl[BN*VD*HH];
__device__ bf16 g_xagh[BN*HH],    g_xagl[BN*HH];
#define WROWS 3840
__device__ bf16 g_wh[WROWS*HH], g_wl[WROWS*HH];

// ---------------- CSR scratch -------------------------------------------------
__device__ int g_rowstart[BN + 1];
__device__ int g_elist[EE];

// weight row offsets within g_wh/g_wl
#define OFF_WQ   0
#define OFF_WK   256
#define OFF_WV   512
#define OFF_WAO  768
#define OFF_WDV  1024
#define OFF_WF   1280
#define OFF_WS   1536
#define OFF_WVEC 2048
#define OFF_WO   2560
#define OFF_WTRG 3328
#define OFF_WSRC 3584

__device__ __forceinline__ float silu_f(float x) { return x / (1.f + __expf(-x)); }
__device__ __forceinline__ float cut_f(float rr) {
    return (rr < 5.f) ? 0.5f * (cosf(rr * 0.6283185307179586f) + 1.f) : 0.f;
}

__device__ __forceinline__ uint32_t smem_u32(const void* p) {
    uint32_t a;
    asm("{ .reg .u64 t; cvta.to.shared.u64 t, %1; cvt.u32.u64 %0, t; }" : "=r"(a) : "l"(p));
    return a;
}

// ---------------- mma.sync / ldmatrix / cp.async wrappers --------------------
__device__ __forceinline__ void ldsm4(uint32_t* r, uint32_t addr) {
    asm volatile("ldmatrix.sync.aligned.m8n8.x4.shared.b16 {%0,%1,%2,%3}, [%4];"
                 : "=r"(r[0]), "=r"(r[1]), "=r"(r[2]), "=r"(r[3]) : "r"(addr));
}
__device__ __forceinline__ void mma_bf16(float* d, const uint32_t* a, const uint32_t* b) {
    asm volatile("mma.sync.aligned.m16n8k16.row.col.f32.bf16.bf16.f32 "
                 "{%0,%1,%2,%3}, {%4,%5,%6,%7}, {%8,%9}, {%0,%1,%2,%3};"
                 : "+f"(d[0]), "+f"(d[1]), "+f"(d[2]), "+f"(d[3])
                 : "r"(a[0]), "r"(a[1]), "r"(a[2]), "r"(a[3]), "r"(b[0]), "r"(b[1]));
}
#define CP_COMMIT() asm volatile("cp.async.commit_group;" ::: "memory")

// =============================================================================
// Unified job-table GEMM, 128x64 tiles (96KB smem -> 2 CTAs/SM), persistent
// grid-stride over totalTiles so a bounded grid can own a bounded SM subset.
// Mode 0: C = [silu](A@W^T + bias) fp32.
// Mode 1: vj epilogue silu(acc+bias)*cut(r[row])*v[src[row]][col] -> bf16 hi/lo.
// =============================================================================
struct GJob {
    const bf16 *Ah, *Al, *Bh, *Bl;
    const float* bias;
    float* C;
    int Nfull, colTiles, silu, tileOfs;
};
struct GArgs {
    GJob jobs[7];
    int njobs;
    int mode;
    int totalTiles;
    const float* vsrc; const int* srcidx; const float* rij;
    bf16 *Oh, *Ol;
};

#define CHUNK_BYTES 49152
#define MG_SMEM (2 * CHUNK_BYTES)   // 96 KB

__device__ __forceinline__ void cp_tileA(uint32_t dst_s, const bf16* __restrict__ src,
                                         int rowbase, int kc, int tid)
{
    const char* g = (const char*)(src + (size_t)rowbase * HH + kc * 64);
#pragma unroll
    for (int it = 0; it < 4; it++) {
        int u   = tid + it * 256;       // 1024 units: 128 rows x 8
        int row = u >> 3;
        int ui  = u & 7;
        uint32_t off = row * 128 + ui * 16;
        off ^= (off >> 3) & 0x70;
        asm volatile("cp.async.cg.shared.global [%0], [%1], 16;"
                     :: "r"(dst_s + off), "l"(g + (size_t)row * 512 + ui * 16));
    }
}
__device__ __forceinline__ void cp_tileB(uint32_t dst_s, const bf16* __restrict__ src,
                                         int rowbase, int kc, int tid)
{
    const char* g = (const char*)(src + (size_t)rowbase * HH + kc * 64);
#pragma unroll
    for (int it = 0; it < 2; it++) {
        int u   = tid + it * 256;       // 512 units: 64 rows x 8
        int row = u >> 3;
        int ui  = u & 7;
        uint32_t off = row * 128 + ui * 16;
        off ^= (off >> 3) & 0x70;
        asm volatile("cp.async.cg.shared.global [%0], [%1], 16;"
                     :: "r"(dst_s + off), "l"(g + (size_t)row * 512 + ui * 16));
    }
}

__device__ __forceinline__ void cp_chunk(uint32_t sbase,
    const bf16* Ah, const bf16* Al, const bf16* Bh, const bf16* Bl,
    int rowA, int colB, int kc, int tid)
{
    cp_tileA(sbase,         Ah, rowA, kc, tid);
    cp_tileA(sbase + 16384, Al, rowA, kc, tid);
    cp_tileB(sbase + 32768, Bh, colB, kc, tid);
    cp_tileB(sbase + 40960, Bl, colB, kc, tid);
}

__global__ __launch_bounds__(256) void gemm_kernel(GArgs P)
{
    extern __shared__ uint8_t smem[];
    const int tid = threadIdx.x, wid = tid >> 5, lane = tid & 31;
    const int wr = wid >> 1, wc = wid & 1;   // warp tile: 32 rows x 32 cols

    uint32_t aoff[2], boff[2];
#pragma unroll
    for (int i = 0; i < 2; i++)
        aoff[i] = (uint32_t)((wr * 32 + i * 16 + (lane & 15)) * 128 + (lane >> 4) * 16);
    {
        int grp = lane >> 3, lr = lane & 7;
#pragma unroll
        for (int j2 = 0; j2 < 2; j2++)
            boff[j2] = (uint32_t)((wc * 32 + j2 * 16 + (grp >> 1) * 8 + lr) * 128
                                  + (grp & 1) * 16);
    }
    const uint32_t sb = smem_u32(smem);
    const int r0 = lane >> 2, c0 = (lane & 3) * 2;

    for (int tile = blockIdx.x; tile < P.totalTiles; tile += gridDim.x) {

        int j = 0;
#pragma unroll
        for (int jj = 1; jj < 7; jj++)
            if (jj < P.njobs && tile >= P.jobs[jj].tileOfs) j = jj;
        const GJob job = P.jobs[j];
        const int local = tile - job.tileOfs;
        const int rowA = (local / job.colTiles) * 128;
        const int colB = (local % job.colTiles) * 64;

        const bf16* __restrict__ Ah = job.Ah;
        const bf16* __restrict__ Al = job.Al;
        const bf16* __restrict__ Bh = job.Bh;
        const bf16* __restrict__ Bl = job.Bl;

        float acc[2][4][4];
#pragma unroll
        for (int i = 0; i < 2; i++)
#pragma unroll
            for (int jj = 0; jj < 4; jj++)
#pragma unroll
                for (int r = 0; r < 4; r++) acc[i][jj][r] = 0.f;

        cp_chunk(sb,               Ah, Al, Bh, Bl, rowA, colB, 0, tid); CP_COMMIT();
        cp_chunk(sb + CHUNK_BYTES, Ah, Al, Bh, Bl, rowA, colB, 1, tid); CP_COMMIT();

        int buf = 0;
        for (int kc = 0; kc < 4; kc++) {
            if (kc < 3) asm volatile("cp.async.wait_group 1;" ::: "memory");
            else        asm volatile("cp.async.wait_group 0;" ::: "memory");
            __syncthreads();
            const uint32_t base = sb + buf * CHUNK_BYTES;
#pragma unroll
            for (int ks = 0; ks < 4; ks++) {
                const uint32_t kb = ks * 32;
                uint32_t ahf[2][4], alf[2][4], bhf[2][4], blf[2][4];
#pragma unroll
                for (int i = 0; i < 2; i++) {
                    uint32_t o = aoff[i] + kb; o ^= (o >> 3) & 0x70;
                    ldsm4(ahf[i], base + o);
                    ldsm4(alf[i], base + 16384 + o);
                }
#pragma unroll
                for (int j2 = 0; j2 < 2; j2++) {
                    uint32_t o = boff[j2] + kb; o ^= (o >> 3) & 0x70;
                    ldsm4(bhf[j2], base + 32768 + o);
                    ldsm4(blf[j2], base + 40960 + o);
                }
#pragma unroll
                for (int i = 0; i < 2; i++)
#pragma unroll
                    for (int jj = 0; jj < 4; jj++) {
                        const uint32_t* b_hi = &bhf[jj >> 1][(jj & 1) * 2];
                        const uint32_t* b_lo = &blf[jj >> 1][(jj & 1) * 2];
                        mma_bf16(acc[i][jj], ahf[i], b_hi);
                        mma_bf16(acc[i][jj], ahf[i], b_lo);
                        mma_bf16(acc[i][jj], alf[i], b_hi);
                    }
            }
            __syncthreads();
            if (kc + 2 <= 3) {
                cp_chunk(sb + buf * CHUNK_BYTES, Ah, Al, Bh, Bl, rowA, colB, kc + 2, tid);
                CP_COMMIT();
            }
            buf ^= 1;
        }

        const float* bias = job.bias;

        if (P.mode == 1) {
            __nv_bfloat162* OH = (__nv_bfloat162*)P.Oh;
            __nv_bfloat162* OL = (__nv_bfloat162*)P.Ol;
#pragma unroll
            for (int i = 0; i < 2; i++) {
                const int row0 = rowA + wr * 32 + i * 16 + r0;
                const int row1 = row0 + 8;
                const int s0 = P.srcidx[row0], s1i = P.srcidx[row1];
                const float cut0 = cut_f(P.rij[row0]);
                const float cut1 = cut_f(P.rij[row1]);
#pragma unroll
                for (int jj = 0; jj < 4; jj++) {
                    const int gcol = colB + wc * 32 + jj * 8 + c0;
                    const float b0 = bias[gcol], b1 = bias[gcol + 1];
                    float v0 = silu_f(acc[i][jj][0] + b0) * cut0 * P.vsrc[(size_t)s0 * HH + gcol];
                    float v1 = silu_f(acc[i][jj][1] + b1) * cut0 * P.vsrc[(size_t)s0 * HH + gcol + 1];
                    float v2 = silu_f(acc[i][jj][2] + b0) * cut1 * P.vsrc[(size_t)s1i * HH + gcol];
                    float v3 = silu_f(acc[i][jj][3] + b1) * cut1 * P.vsrc[(size_t)s1i * HH + gcol + 1];
                    bf16 h0 = __float2bfloat16(v0), h1 = __float2bfloat16(v1);
                    bf16 h2 = __float2bfloat16(v2), h3 = __float2bfloat16(v3);
                    bf16 l0 = __float2bfloat16(v0 - __bfloat162float(h0));
                    bf16 l1 = __float2bfloat16(v1 - __bfloat162float(h1));
                    bf16 l2 = __float2bfloat16(v2 - __bfloat162float(h2));
                    bf16 l3 = __float2bfloat16(v3 - __bfloat162float(h3));
                    OH[(size_t)row0 * 128 + (gcol >> 1)] = __nv_bfloat162(h0, h1);
                    OL[(size_t)row0 * 128 + (gcol >> 1)] = __nv_bfloat162(l0, l1);
                    OH[(size_t)row1 * 128 + (gcol >> 1)] = __nv_bfloat162(h2, h3);
                    OL[(size_t)row1 * 128 + (gcol >> 1)] = __nv_bfloat162(l2, l3);
                }
            }
        } else {
            float* __restrict__ C = job.C;
            const int Nfull = job.Nfull;
            const int do_silu = job.silu;
#pragma unroll
            for (int i = 0; i < 2; i++) {
                const int grow = rowA + wr * 32 + i * 16 + r0;
#pragma unroll
                for (int jj = 0; jj < 4; jj++) {
                    const int gcol = colB + wc * 32 + jj * 8 + c0;
                    float b0 = bias[gcol], b1 = bias[gcol + 1];
                    float v0 = acc[i][jj][0] + b0, v1 = acc[i][jj][1] + b1;
                    float v2 = acc[i][jj][2] + b0, v3 = acc[i][jj][3] + b1;
                    if (do_silu) {
                        v0 = silu_f(v0); v1 = silu_f(v1); v2 = silu_f(v2); v3 = silu_f(v3);
                    }
                    *(float2*)(C + (size_t)grow * Nfull + gcol)       = make_float2(v0, v1);
                    *(float2*)(C + (size_t)(grow + 8) * Nfull + gcol) = make_float2(v2, v3);
                }
            }
        }
        __syncthreads();
    }
}

// =============================================================================
// prep_kernel: wprep (8448) | conv fij (4096) | conv vec (4096) | ln (2048) | CSR (1)
// =============================================================================
struct PrepArgs {
    const float* wsrc[11]; int wN[11]; int woff[11];
    const float* f_ij; const float* vec; const float* x;
    const float* ln_w; const float* ln_b; const int* dst;
};

__device__ __forceinline__ void conv_body(int i, const float* __restrict__ in,
                                          bf16* hi, bf16* lo)
{
    float4 v = ((const float4*)in)[i];
    bf16 h0 = __float2bfloat16(v.x), h1 = __float2bfloat16(v.y);
    bf16 h2 = __float2bfloat16(v.z), h3 = __float2bfloat16(v.w);
    bf16 l0 = __float2bfloat16(v.x - __bfloat162float(h0));
    bf16 l1 = __float2bfloat16(v.y - __bfloat162float(h1));
    bf16 l2 = __float2bfloat16(v.z - __bfloat162float(h2));
    bf16 l3 = __float2bfloat16(v.w - __bfloat162float(h3));
    __nv_bfloat162* hp = (__nv_bfloat162*)hi;
    __nv_bfloat162* lp = (__nv_bfloat162*)lo;
    hp[2 * i]     = __nv_bfloat162(h0, h1);
    hp[2 * i + 1] = __nv_bfloat162(h2, h3);
    lp[2 * i]     = __nv_bfloat162(l0, l1);
    lp[2 * i + 1] = __nv_bfloat162(l2, l3);
}

#define PREP_WP   8448
#define PREP_CF   4096
#define PREP_CV   4096
#define PREP_LN   2048
#define PREP_TOT  (PREP_WP + PREP_CF + PREP_CV + PREP_LN + 1)

__global__ __launch_bounds__(256) void prep_kernel(PrepArgs P)
{
    __shared__ int csr_s[BN];
    __shared__ float red[8];
    int bx = blockIdx.x;
    const int t = threadIdx.x;

    if (bx < PREP_WP) {               // weight prep
        int w = bx / 768, n = bx % 768;
        if (n < P.wN[w]) {
            float v = P.wsrc[w][(size_t)t * P.wN[w] + n];
            bf16 h = __float2bfloat16(v);
            bf16 l = __float2bfloat16(v - __bfloat162float(h));
            size_t o = (size_t)(P.woff[w] + n) * HH + t;
            g_wh[o] = h; g_wl[o] = l;
        }
        return;
    }
    bx -= PREP_WP;
    if (bx < PREP_CF) { conv_body(bx * 256 + t, P.f_ij, g_fijh, g_fijl); return; }
    bx -= PREP_CF;
    if (bx < PREP_CV) { conv_body(bx * 256 + t, P.vec, g_vech, g_vecl); return; }
    bx -= PREP_CV;
    if (bx < PREP_LN) {               // LayerNorm
        int n = bx;
        float v = P.x[n * HH + t];
        float s = v;
#pragma unroll
        for (int o = 16; o; o >>= 1) s += __shfl_xor_sync(0xffffffffu, s, o);
        if ((t & 31) == 0) red[t >> 5] = s;
        __syncthreads();
        float tot = 0.f;
#pragma unroll
        for (int i = 0; i < 8; i++) tot += red[i];
        float mu = tot * (1.f / HH);
        float dv = v - mu;
        float s2 = dv * dv;
#pragma unroll
        for (int o = 16; o; o >>= 1) s2 += __shfl_xor_sync(0xffffffffu, s2, o);
        __syncthreads();
        if ((t & 31) == 0) red[t >> 5] = s2;
        __syncthreads();
        float var = 0.f;
#pragma unroll
        for (int i = 0; i < 8; i++) var += red[i];
        var *= (1.f / HH);
        float xn = dv * rsqrtf(var + 1e-5f) * P.ln_w[t] + P.ln_b[t];
        bf16 hh2 = __float2bfloat16(xn);
        g_xnh[n * HH + t] = hh2;
        g_xnl[n * HH + t] = __float2bfloat16(xn - __bfloat162float(hh2));
        return;
    }

    // ---- CSR build (single block) ----
    for (int i = t; i < BN; i += 256) csr_s[i] = 0;
    __syncthreads();
    const int4* d4 = (const int4*)P.dst;
#pragma unroll
    for (int i = 0; i < 16; i++) {
        int4 v = d4[t * 16 + i];
        atomicAdd(&csr_s[v.x], 1); atomicAdd(&csr_s[v.y], 1);
        atomicAdd(&csr_s[v.z], 1); atomicAdd(&csr_s[v.w], 1);
    }
    __syncthreads();
    for (int d = 1; d < BN; d <<= 1) {
        for (int i = t; i < BN / (2 * d); i += 256) {
            int idx = (i + 1) * 2 * d - 1;
            csr_s[idx] += csr_s[idx - d];
        }
        __syncthreads();
    }
    if (t == 0) { g_rowstart[BN] = csr_s[BN - 1]; csr_s[BN - 1] = 0; }
    __syncthreads();
    for (int d = BN / 2; d >= 1; d >>= 1) {
        for (int i = t; i < BN / (2 * d); i += 256) {
            int idx = (i + 1) * 2 * d - 1;
            int a = csr_s[idx - d];
            csr_s[idx - d] = csr_s[idx];
            csr_s[idx] += a;
        }
        __syncthreads();
    }
    for (int i = t; i < BN; i += 256) g_rowstart[i] = csr_s[i];
    __syncthreads();
#pragma unroll
    for (int i = 0; i < 16; i++) {
        int4 v = d4[t * 16 + i];
        int e = t * 64 + i * 4;
        int p0 = atomicAdd(&csr_s[v.x], 1); g_elist[p0] = e;
        int p1 = atomicAdd(&csr_s[v.y], 1); g_elist[p1] = e + 1;
        int p2 = atomicAdd(&csr_s[v.z], 1); g_elist[p2] = e + 2;
        int p3 = atomicAdd(&csr_s[v.w], 1); g_elist[p3] = e + 3;
    }
}

// =============================================================================
// attention (64 blocks)
// =============================================================================
__global__ __launch_bounds__(256) void attn_kernel()
{
    __shared__ float ks[64][32];
    __shared__ float vs[64][32];
    int b = blockIdx.x >> 3;
    int hd = blockIdx.x & 7;
    int i = threadIdx.x;
    float qr[32];
    const float* qrow = g_q + (size_t)(b * NN + i) * HH + hd * HD;
#pragma unroll
    for (int d = 0; d < 32; d++) qr[d] = qrow[d];
    float acc[32];
#pragma unroll
    for (int d = 0; d < 32; d++) acc[d] = 0.f;
    const float scale = rsqrtf((float)HD);

    for (int j0 = 0; j0 < NN; j0 += 64) {
        __syncthreads();
        for (int l = threadIdx.x; l < 512; l += 256) {
            int jr = l >> 3;
            int dc = (l & 7) * 4;
            size_t base = (size_t)(b * NN + j0 + jr) * HH + hd * HD + dc;
            *(float4*)&ks[jr][dc] = *(const float4*)&g_k[base];
            *(float4*)&vs[jr][dc] = *(const float4*)&g_vv[base];
        }
        __syncthreads();
        for (int j = 0; j < 64; j++) {
            float s = 0.f;
#pragma unroll
            for (int d = 0; d < 32; d++) s += qr[d] * ks[j][d];
            s = silu_f(s * scale);
#pragma unroll
            for (int d = 0; d < 32; d++) acc[d] += s * vs[j][d];
        }
    }
    size_t base = (size_t)(b * NN + i) * HH + hd * HD;
#pragma unroll
    for (int d = 0; d < 32; d++) {
        float val = acc[d] * (1.f / NN);
        bf16 h2 = __float2bfloat16(val);
        g_vath[base + d] = h2;
        g_vatl[base + d] = __float2bfloat16(val - __bfloat162float(h2));
    }
}

// =============================================================================
// wdot (EE blocks)
// =============================================================================
__global__ __launch_bounds__(256) void wdot_kernel(
    const int* __restrict__ src, const int* __restrict__ dst,
    const float* __restrict__ dij, float* __restrict__ df)
{
    __shared__ float dsh[VD];
    int e = blockIdx.x;
    int h = threadIdx.x;
    if (h < VD) dsh[h] = dij[e * VD + h];
    __syncthreads();
    int s = src[e], tt = dst[e];
    float tv[VD], sv[VD];
    float pT = 0.f, pS = 0.f;
#pragma unroll
    for (int vd = 0; vd < VD; vd++) {
        tv[vd] = g_T[(size_t)(tt * VD + vd) * HH + h];
        sv[vd] = g_S[(size_t)(s * VD + vd) * HH + h];
        pT += tv[vd] * dsh[vd];
        pS += sv[vd] * dsh[vd];
    }
    float wd = 0.f;
#pragma unroll
    for (int vd = 0; vd < VD; vd++)
        wd += (tv[vd] - pT * dsh[vd]) * (sv[vd] - pS * dsh[vd]);
    df[(size_t)e * HH + h] = g_ff[(size_t)e * HH + h] * wd;
}

// ======================= gather: x_agg + dvec (no atomics) ===================
__global__ __launch_bounds__(256) void gather_kernel(
    const float* __restrict__ s12, const float* __restrict__ vec,
    const float* __restrict__ dij, const int* __restrict__ src,
    float* __restrict__ dvec_out)
{
    int n = blockIdx.x, h = threadIdx.x;
    int beg = g_rowstart[n], end = g_rowstart[n + 1];
    float xa = 0.f;
    float dv[VD];
#pragma unroll
    for (int vd = 0; vd < VD; vd++) dv[vd] = 0.f;

    for (int i = beg; i < end; i++) {
        int e = g_elist[i];
        int s = src[e];
        float vje = __bfloat162float(g_vjh[(size_t)e * HH + h]) +
                    __bfloat162float(g_vjl[(size_t)e * HH + h]);
        xa += vje;
        float s1  = s12[(size_t)e * (2 * HH) + h];
        float s2v = s12[(size_t)e * (2 * HH) + HH + h];
#pragma unroll
        for (int vd = 0; vd < VD; vd++)
            dv[vd] += vec[(size_t)s * (VD * HH) + vd * HH + h] * s1
                    + s2v * dij[e * VD + vd];
    }
    bf16 hh = __float2bfloat16(xa);
    g_xagh[n * HH + h] = hh;
    g_xagl[n * HH + h] = __float2bfloat16(xa - __bfloat162float(hh));
#pragma unroll
    for (int vd = 0; vd < VD; vd++)
        dvec_out[(size_t)n * (VD * HH) + vd * HH + h] = dv[vd];
}

// ======================= finalize ============================================
__global__ __launch_bounds__(256) void finalize_kernel(float* __restrict__ dx,
                                                       float* __restrict__ dvec)
{
    int n = blockIdx.x, h = threadIdx.x;
    float o1 = g_o[(size_t)n * (3 * HH) + h];
    float o2 = g_o[(size_t)n * (3 * HH) + HH + h];
    float o3 = g_o[(size_t)n * (3 * HH) + 2 * HH + h];
    float vsum = 0.f;
#pragma unroll
    for (int vd = 0; vd < VD; vd++)
        vsum += g_vp[(size_t)(n * VD + vd) * (2 * HH) + h];
    dx[n * HH + h] = vsum * o2 + o3;
#pragma unroll
    for (int vd = 0; vd < VD; vd++) {
        float vec3 = g_vp[(size_t)(n * VD + vd) * (2 * HH) + HH + h];
        dvec[(size_t)n * (VD * HH) + vd * HH + h] += vec3 * o1;
    }
}

// ======================= launcher ============================================
extern "C" void kernel_launch(void* const* d_in, const int* in_sizes, int n_in,
                              void* d_out, int out_size)
{
    const float* x    = (const float*)d_in[0];
    const float* vec  = (const float*)d_in[1];
    const int*   ei   = (const int*)d_in[2];
    const float* r_ij = (const float*)d_in[3];
    const float* f_ij = (const float*)d_in[4];
    const float* d_ij = (const float*)d_in[5];
    const float* ln_w = (const float*)d_in[7];
    const float* ln_b = (const float*)d_in[8];
    const float* Wq   = (const float*)d_in[9];
    const float* Wk   = (const float*)d_in[10];
    const float* Wv   = (const float*)d_in[11];
    const float* Wao  = (const float*)d_in[12];
    const float* Wvec = (const float*)d_in[13];
    const float* Wdv  = (const float*)d_in[14];
    const float* bdv  = (const float*)d_in[15];
    const float* Ws   = (const float*)d_in[16];
    const float* bs   = (const float*)d_in[17];
    const float* Wo   = (const float*)d_in[18];
    const float* bo   = (const float*)d_in[19];
    const float* Wf   = (const float*)d_in[20];
    const float* bf   = (const float*)d_in[21];
    const float* Wsrc = (const float*)d_in[22];
    const float* Wtrg = (const float*)d_in[23];

    const int* src = ei;
    const int* dst = ei + EE;

    float* out      = (float*)d_out;
    float* out_dx   = out;
    float* out_dvec = out + (size_t)BN * HH;
    float* out_df   = out_dvec + (size_t)BN * VD * HH;

    float *p_q, *p_k, *p_vv, *p_v, *p_vp, *p_s12, *p_o, *p_T, *p_S, *p_ff, *p_zb;
    bf16 *p_xnh, *p_xnl, *p_vath, *p_vatl, *p_fijh, *p_fijl, *p_vjh, *p_vjl,
         *p_vech, *p_vecl, *p_xagh, *p_xagl, *p_wh, *p_wl;
    cudaGetSymbolAddress((void**)&p_q,    g_q);
    cudaGetSymbolAddress((void**)&p_k,    g_k);
    cudaGetSymbolAddress((void**)&p_vv,   g_vv);
    cudaGetSymbolAddress((void**)&p_v,    g_v);
    cudaGetSymbolAddress((void**)&p_vp,   g_vp);
    cudaGetSymbolAddress((void**)&p_s12,  g_s12);
    cudaGetSymbolAddress((void**)&p_o,    g_o);
    cudaGetSymbolAddress((void**)&p_T,    g_T);
    cudaGetSymbolAddress((void**)&p_S,    g_S);
    cudaGetSymbolAddress((void**)&p_ff,   g_ff);
    cudaGetSymbolAddress((void**)&p_zb,   g_zb);
    cudaGetSymbolAddress((void**)&p_xnh,  g_xnh);
    cudaGetSymbolAddress((void**)&p_xnl,  g_xnl);
    cudaGetSymbolAddress((void**)&p_vath, g_vath);
    cudaGetSymbolAddress((void**)&p_vatl, g_vatl);
    cudaGetSymbolAddress((void**)&p_fijh, g_fijh);
    cudaGetSymbolAddress((void**)&p_fijl, g_fijl);
    cudaGetSymbolAddress((void**)&p_vjh,  g_vjh);
    cudaGetSymbolAddress((void**)&p_vjl,  g_vjl);
    cudaGetSymbolAddress((void**)&p_vech, g_vech);
    cudaGetSymbolAddress((void**)&p_vecl, g_vecl);
    cudaGetSymbolAddress((void**)&p_xagh, g_xagh);
    cudaGetSymbolAddress((void**)&p_xagl, g_xagl);
    cudaGetSymbolAddress((void**)&p_wh,   g_wh);
    cudaGetSymbolAddress((void**)&p_wl,   g_wl);

    cudaFuncSetAttribute(gemm_kernel, cudaFuncAttributeMaxDynamicSharedMemorySize, MG_SMEM);

    auto WH = [&](int off) { return p_wh + (size_t)off * HH; };
    auto WL = [&](int off) { return p_wl + (size_t)off * HH; };

    // fork/join stream + events
    cudaStream_t s2;
    cudaStreamCreateWithFlags(&s2, cudaStreamNonBlocking);
    cudaEvent_t evA, evB, evC;
    cudaEventCreateWithFlags(&evA, cudaEventDisableTiming);
    cudaEventCreateWithFlags(&evB, cudaEventDisableTiming);
    cudaEventCreateWithFlags(&evC, cudaEventDisableTiming);

    // ---- 1. prep (wprep + convs + ln + CSR) on stream 0 ----
    {
        PrepArgs P{};
        const float* srcs[11] = {Wq, Wk, Wv, Wao, Wdv, Wf, Ws, Wvec, Wo, Wtrg, Wsrc};
        int ns[11]   = {256, 256, 256, 256, 256, 256, 512, 512, 768, 256, 256};
        int offs[11] = {OFF_WQ, OFF_WK, OFF_WV, OFF_WAO, OFF_WDV, OFF_WF,
                        OFF_WS, OFF_WVEC, OFF_WO, OFF_WTRG, OFF_WSRC};
        for (int i = 0; i < 11; i++) { P.wsrc[i] = srcs[i]; P.wN[i] = ns[i]; P.woff[i] = offs[i]; }
        P.f_ij = f_ij; P.vec = vec; P.x = x; P.ln_w = ln_w; P.ln_b = ln_b; P.dst = dst;
        prep_kernel<<<PREP_TOT, 256>>>(P);
    }

    // ---- fork: stream2 runs the big independent branch on a BOUNDED grid ----
    cudaEventRecord(evA, 0);
    cudaStreamWaitEvent(s2, evA, 0);

    // stream2: ff/vp/T/S (4 jobs, 2560 tiles) persistent on 96 CTAs (~48 SMs)
    {
        GArgs A{};
        A.njobs = 4; A.mode = 0; A.totalTiles = 2560;
        A.jobs[0] = {p_fijh, p_fijl, WH(OFF_WF),   WL(OFF_WF),   bf,   p_ff, HH,     4, 1, 0};
        A.jobs[1] = {p_vech, p_vecl, WH(OFF_WVEC), WL(OFF_WVEC), p_zb, p_vp, 2 * HH, 8, 0, 512};
        A.jobs[2] = {p_vech, p_vecl, WH(OFF_WTRG), WL(OFF_WTRG), p_zb, p_T,  HH,     4, 0, 1536};
        A.jobs[3] = {p_vech, p_vecl, WH(OFF_WSRC), WL(OFF_WSRC), p_zb, p_S,  HH,     4, 0, 2048};
        gemm_kernel<<<96, 256, MG_SMEM, s2>>>(A);
    }
    cudaEventRecord(evB, s2);                       // ff/vp/T/S ready
    wdot_kernel<<<EE, 256, 0, s2>>>(src, dst, d_ij, out_df);
    cudaEventRecord(evC, s2);                       // branch done

    // ---- stream0 critical chain (full-size launches) ----
    // qkv (3 jobs, 192 tiles)
    {
        GArgs A{};
        A.njobs = 3; A.mode = 0; A.totalTiles = 192;
        A.jobs[0] = {p_xnh, p_xnl, WH(OFF_WQ), WL(OFF_WQ), p_zb, p_q,  HH, 4, 0, 0};
        A.jobs[1] = {p_xnh, p_xnl, WH(OFF_WK), WL(OFF_WK), p_zb, p_k,  HH, 4, 0, 64};
        A.jobs[2] = {p_xnh, p_xnl, WH(OFF_WV), WL(OFF_WV), p_zb, p_vv, HH, 4, 0, 128};
        gemm_kernel<<<192, 256, MG_SMEM>>>(A);
    }

    // attention
    attn_kernel<<<64, 256>>>();

    // v = vatt @ Wao (64 tiles)
    {
        GArgs A{};
        A.njobs = 1; A.mode = 0; A.totalTiles = 64;
        A.jobs[0] = {p_vath, p_vatl, WH(OFF_WAO), WL(OFF_WAO), p_zb, p_v, HH, 4, 0, 0};
        gemm_kernel<<<64, 256, MG_SMEM>>>(A);
    }

    // vj = silu(f_ij @ Wdv + bdv)*cut*v[src] -> bf16 hi/lo (512 tiles)
    {
        GArgs A{};
        A.njobs = 1; A.mode = 1; A.totalTiles = 512;
        A.jobs[0] = {p_fijh, p_fijl, WH(OFF_WDV), WL(OFF_WDV), bdv, nullptr, HH, 4, 0, 0};
        A.vsrc = p_v; A.srcidx = src; A.rij = r_ij; A.Oh = p_vjh; A.Ol = p_vjl;
        gemm_kernel<<<512, 256, MG_SMEM>>>(A);
    }

    // s12 = silu(v_j @ Ws + bs) (1024 tiles)
    {
        GArgs A{};
        A.njobs = 1; A.mode = 0; A.totalTiles = 1024;
        A.jobs[0] = {p_vjh, p_vjl, WH(OFF_WS), WL(OFF_WS), bs, p_s12, 2 * HH, 8, 1, 0};
        gemm_kernel<<<1024, 256, MG_SMEM>>>(A);
    }

    // gather
    gather_kernel<<<BN, 256>>>(p_s12, vec, d_ij, src, out_dvec);

    // o = x_agg @ Wo + bo (192 tiles)
    {
        GArgs A{};
        A.njobs = 1; A.mode = 0; A.totalTiles = 192;
        A.jobs[0] = {p_xagh, p_xagl, WH(OFF_WO), WL(OFF_WO), bo, p_o, 3 * HH, 12, 0, 0};
        gemm_kernel<<<192, 256, MG_SMEM>>>(A);
    }

    // finalize needs vp from stream2 branch
    cudaStreamWaitEvent(0, evB, 0);
    finalize_kernel<<<BN, 256>>>(out_dx, out_dvec);

    // join branch (wdot) before returning
    cudaStreamWaitEvent(0, evC, 0);
}

// round 10
// speedup vs baseline: 1.2033x; 1.1543x over previous
#include <cuda_runtime.h>
#include <cuda_bf16.h>
#include <cstdint>

// Problem constants
#define BB 8
#define NN 256
#define BN 2048          // BB*NN
#define EE 16384
#define HH 256
#define NHD 8
#define HD 32
#define VD 8

typedef __nv_bfloat16 bf16;

// ---------------- fp32 scratch ------------------------------------------------
__device__ float g_q   [BN*HH];
__device__ float g_k   [BN*HH];
__device__ float g_vv  [BN*HH];
__device__ float g_v   [BN*HH];
__device__ float g_vp  [BN*VD*2*HH];
__device__ float g_s12 [EE*2*HH];
__device__ float g_o   [BN*3*HH];
__device__ float g_T   [BN*VD*HH];
__device__ float g_S   [BN*VD*HH];
__device__ float g_ff  [EE*HH];
__device__ float g_zb  [3*HH];          // zero bias (static zero-init)

// ---------------- bf16 hi/lo scratch -----------------------------------------
__device__ bf16 g_xnh [BN*HH],    g_xnl [BN*HH];
__device__ bf16 g_vath[BN*HH],    g_vatl[BN*HH];
__device__ bf16 g_fijh[EE*HH],    g_fijl[EE*HH];
__device__ bf16 g_vjh [EE*HH],    g_vjl [EE*HH];
__device__ bf16 g_vech[BN*VD*HH], g_vecl[BN*VD*HH];
__device__ bf16 g_xagh[BN*HH],    g_xagl[BN*HH];
#define WROWS 3840
__device__ bf16 g_wh[WROWS*HH], g_wl[WROWS*HH];

// ---------------- CSR scratch -------------------------------------------------
__device__ int g_rowstart[BN + 1];
__device__ int g_elist[EE];

// weight row offsets within g_wh/g_wl
#define OFF_WQ   0
#define OFF_WK   256
#define OFF_WV   512
#define OFF_WAO  768
#define OFF_WDV  1024
#define OFF_WF   1280
#define OFF_WS   1536
#define OFF_WVEC 2048
#define OFF_WO   2560
#define OFF_WTRG 3328
#define OFF_WSRC 3584

__device__ __forceinline__ float silu_f(float x) { return x / (1.f + __expf(-x)); }
__device__ __forceinline__ float cut_f(float rr) {
    return (rr < 5.f) ? 0.5f * (cosf(rr * 0.6283185307179586f) + 1.f) : 0.f;
}

__device__ __forceinline__ uint32_t smem_u32(const void* p) {
    uint32_t a;
    asm("{ .reg .u64 t; cvta.to.shared.u64 t, %1; cvt.u32.u64 %0, t; }" : "=r"(a) : "l"(p));
    return a;
}

// ---------------- mma.sync / ldmatrix / cp.async wrappers --------------------
__device__ __forceinline__ void ldsm4(uint32_t* r, uint32_t addr) {
    asm volatile("ldmatrix.sync.aligned.m8n8.x4.shared.b16 {%0,%1,%2,%3}, [%4];"
                 : "=r"(r[0]), "=r"(r[1]), "=r"(r[2]), "=r"(r[3]) : "r"(addr));
}
__device__ __forceinline__ void mma_bf16(float* d, const uint32_t* a, const uint32_t* b) {
    asm volatile("mma.sync.aligned.m16n8k16.row.col.f32.bf16.bf16.f32 "
                 "{%0,%1,%2,%3}, {%4,%5,%6,%7}, {%8,%9}, {%0,%1,%2,%3};"
                 : "+f"(d[0]), "+f"(d[1]), "+f"(d[2]), "+f"(d[3])
                 : "r"(a[0]), "r"(a[1]), "r"(a[2]), "r"(a[3]), "r"(b[0]), "r"(b[1]));
}
#define CP_COMMIT() asm volatile("cp.async.commit_group;" ::: "memory")

// =============================================================================
// Unified job-table GEMM, 128x64 tiles (96KB smem -> 2 CTAs/SM), persistent
// grid-stride over totalTiles.
// Mode 0: C = [silu](A@W^T + bias) fp32.
// Mode 1: vj epilogue silu(acc+bias)*cut(r[row])*v[src[row]][col] -> bf16 hi/lo.
// =============================================================================
struct GJob {
    const bf16 *Ah, *Al, *Bh, *Bl;
    const float* bias;
    float* C;
    int Nfull, colTiles, silu, tileOfs;
};
struct GArgs {
    GJob jobs[7];
    int njobs;
    int mode;
    int totalTiles;
    const float* vsrc; const int* srcidx; const float* rij;
    bf16 *Oh, *Ol;
};

#define CHUNK_BYTES 49152
#define MG_SMEM (2 * CHUNK_BYTES)   // 96 KB

__device__ __forceinline__ void cp_tileA(uint32_t dst_s, const bf16* __restrict__ src,
                                         int rowbase, int kc, int tid)
{
    const char* g = (const char*)(src + (size_t)rowbase * HH + kc * 64);
#pragma unroll
    for (int it = 0; it < 4; it++) {
        int u   = tid + it * 256;       // 1024 units: 128 rows x 8
        int row = u >> 3;
        int ui  = u & 7;
        uint32_t off = row * 128 + ui * 16;
        off ^= (off >> 3) & 0x70;
        asm volatile("cp.async.cg.shared.global [%0], [%1], 16;"
                     :: "r"(dst_s + off), "l"(g + (size_t)row * 512 + ui * 16));
    }
}
__device__ __forceinline__ void cp_tileB(uint32_t dst_s, const bf16* __restrict__ src,
                                         int rowbase, int kc, int tid)
{
    const char* g = (const char*)(src + (size_t)rowbase * HH + kc * 64);
#pragma unroll
    for (int it = 0; it < 2; it++) {
        int u   = tid + it * 256;       // 512 units: 64 rows x 8
        int row = u >> 3;
        int ui  = u & 7;
        uint32_t off = row * 128 + ui * 16;
        off ^= (off >> 3) & 0x70;
        asm volatile("cp.async.cg.shared.global [%0], [%1], 16;"
                     :: "r"(dst_s + off), "l"(g + (size_t)row * 512 + ui * 16));
    }
}

__device__ __forceinline__ void cp_chunk(uint32_t sbase,
    const bf16* Ah, const bf16* Al, const bf16* Bh, const bf16* Bl,
    int rowA, int colB, int kc, int tid)
{
    cp_tileA(sbase,         Ah, rowA, kc, tid);
    cp_tileA(sbase + 16384, Al, rowA, kc, tid);
    cp_tileB(sbase + 32768, Bh, colB, kc, tid);
    cp_tileB(sbase + 40960, Bl, colB, kc, tid);
}

__global__ __launch_bounds__(256) void gemm_kernel(GArgs P)
{
    extern __shared__ uint8_t smem[];
    const int tid = threadIdx.x, wid = tid >> 5, lane = tid & 31;
    const int wr = wid >> 1, wc = wid & 1;   // warp tile: 32 rows x 32 cols

    uint32_t aoff[2], boff[2];
#pragma unroll
    for (int i = 0; i < 2; i++)
        aoff[i] = (uint32_t)((wr * 32 + i * 16 + (lane & 15)) * 128 + (lane >> 4) * 16);
    {
        int grp = lane >> 3, lr = lane & 7;
#pragma unroll
        for (int j2 = 0; j2 < 2; j2++)
            boff[j2] = (uint32_t)((wc * 32 + j2 * 16 + (grp >> 1) * 8 + lr) * 128
                                  + (grp & 1) * 16);
    }
    const uint32_t sb = smem_u32(smem);
    const int r0 = lane >> 2, c0 = (lane & 3) * 2;

    for (int tile = blockIdx.x; tile < P.totalTiles; tile += gridDim.x) {

        int j = 0;
#pragma unroll
        for (int jj = 1; jj < 7; jj++)
            if (jj < P.njobs && tile >= P.jobs[jj].tileOfs) j = jj;
        const GJob job = P.jobs[j];
        const int local = tile - job.tileOfs;
        const int rowA = (local / job.colTiles) * 128;
        const int colB = (local % job.colTiles) * 64;

        const bf16* __restrict__ Ah = job.Ah;
        const bf16* __restrict__ Al = job.Al;
        const bf16* __restrict__ Bh = job.Bh;
        const bf16* __restrict__ Bl = job.Bl;

        float acc[2][4][4];
#pragma unroll
        for (int i = 0; i < 2; i++)
#pragma unroll
            for (int jj = 0; jj < 4; jj++)
#pragma unroll
                for (int r = 0; r < 4; r++) acc[i][jj][r] = 0.f;

        cp_chunk(sb,               Ah, Al, Bh, Bl, rowA, colB, 0, tid); CP_COMMIT();
        cp_chunk(sb + CHUNK_BYTES, Ah, Al, Bh, Bl, rowA, colB, 1, tid); CP_COMMIT();

        int buf = 0;
        for (int kc = 0; kc < 4; kc++) {
            if (kc < 3) asm volatile("cp.async.wait_group 1;" ::: "memory");
            else        asm volatile("cp.async.wait_group 0;" ::: "memory");
            __syncthreads();
            const uint32_t base = sb + buf * CHUNK_BYTES;
#pragma unroll
            for (int ks = 0; ks < 4; ks++) {
                const uint32_t kb = ks * 32;
                uint32_t ahf[2][4], alf[2][4], bhf[2][4], blf[2][4];
#pragma unroll
                for (int i = 0; i < 2; i++) {
                    uint32_t o = aoff[i] + kb; o ^= (o >> 3) & 0x70;
                    ldsm4(ahf[i], base + o);
                    ldsm4(alf[i], base + 16384 + o);
                }
#pragma unroll
                for (int j2 = 0; j2 < 2; j2++) {
                    uint32_t o = boff[j2] + kb; o ^= (o >> 3) & 0x70;
                    ldsm4(bhf[j2], base + 32768 + o);
                    ldsm4(blf[j2], base + 40960 + o);
                }
                // Pass 1: all 8 independent Ahi*Bhi
#pragma unroll
                for (int i = 0; i < 2; i++)
#pragma unroll
                    for (int jj = 0; jj < 4; jj++)
                        mma_bf16(acc[i][jj], ahf[i], &bhf[jj >> 1][(jj & 1) * 2]);
                // Pass 2: all 8 independent Ahi*Blo
#pragma unroll
                for (int i = 0; i < 2; i++)
#pragma unroll
                    for (int jj = 0; jj < 4; jj++)
                        mma_bf16(acc[i][jj], ahf[i], &blf[jj >> 1][(jj & 1) * 2]);
                // Pass 3: all 8 independent Alo*Bhi
#pragma unroll
                for (int i = 0; i < 2; i++)
#pragma unroll
                    for (int jj = 0; jj < 4; jj++)
                        mma_bf16(acc[i][jj], alf[i], &bhf[jj >> 1][(jj & 1) * 2]);
            }
            __syncthreads();
            if (kc + 2 <= 3) {
                cp_chunk(sb + buf * CHUNK_BYTES, Ah, Al, Bh, Bl, rowA, colB, kc + 2, tid);
                CP_COMMIT();
            }
            buf ^= 1;
        }

        const float* bias = job.bias;

        if (P.mode == 1) {
            __nv_bfloat162* OH = (__nv_bfloat162*)P.Oh;
            __nv_bfloat162* OL = (__nv_bfloat162*)P.Ol;
#pragma unroll
            for (int i = 0; i < 2; i++) {
                const int row0 = rowA + wr * 32 + i * 16 + r0;
                const int row1 = row0 + 8;
                const int s0 = P.srcidx[row0], s1i = P.srcidx[row1];
                const float cut0 = cut_f(P.rij[row0]);
                const float cut1 = cut_f(P.rij[row1]);
#pragma unroll
                for (int jj = 0; jj < 4; jj++) {
                    const int gcol = colB + wc * 32 + jj * 8 + c0;
                    const float b0 = bias[gcol], b1 = bias[gcol + 1];
                    float v0 = silu_f(acc[i][jj][0] + b0) * cut0 * P.vsrc[(size_t)s0 * HH + gcol];
                    float v1 = silu_f(acc[i][jj][1] + b1) * cut0 * P.vsrc[(size_t)s0 * HH + gcol + 1];
                    float v2 = silu_f(acc[i][jj][2] + b0) * cut1 * P.vsrc[(size_t)s1i * HH + gcol];
                    float v3 = silu_f(acc[i][jj][3] + b1) * cut1 * P.vsrc[(size_t)s1i * HH + gcol + 1];
                    bf16 h0 = __float2bfloat16(v0), h1 = __float2bfloat16(v1);
                    bf16 h2 = __float2bfloat16(v2), h3 = __float2bfloat16(v3);
                    bf16 l0 = __float2bfloat16(v0 - __bfloat162float(h0));
                    bf16 l1 = __float2bfloat16(v1 - __bfloat162float(h1));
                    bf16 l2 = __float2bfloat16(v2 - __bfloat162float(h2));
                    bf16 l3 = __float2bfloat16(v3 - __bfloat162float(h3));
                    OH[(size_t)row0 * 128 + (gcol >> 1)] = __nv_bfloat162(h0, h1);
                    OL[(size_t)row0 * 128 + (gcol >> 1)] = __nv_bfloat162(l0, l1);
                    OH[(size_t)row1 * 128 + (gcol >> 1)] = __nv_bfloat162(h2, h3);
                    OL[(size_t)row1 * 128 + (gcol >> 1)] = __nv_bfloat162(l2, l3);
                }
            }
        } else {
            float* __restrict__ C = job.C;
            const int Nfull = job.Nfull;
            const int do_silu = job.silu;
#pragma unroll
            for (int i = 0; i < 2; i++) {
                const int grow = rowA + wr * 32 + i * 16 + r0;
#pragma unroll
                for (int jj = 0; jj < 4; jj++) {
                    const int gcol = colB + wc * 32 + jj * 8 + c0;
                    float b0 = bias[gcol], b1 = bias[gcol + 1];
                    float v0 = acc[i][jj][0] + b0, v1 = acc[i][jj][1] + b1;
                    float v2 = acc[i][jj][2] + b0, v3 = acc[i][jj][3] + b1;
                    if (do_silu) {
                        v0 = silu_f(v0); v1 = silu_f(v1); v2 = silu_f(v2); v3 = silu_f(v3);
                    }
                    *(float2*)(C + (size_t)grow * Nfull + gcol)       = make_float2(v0, v1);
                    *(float2*)(C + (size_t)(grow + 8) * Nfull + gcol) = make_float2(v2, v3);
                }
            }
        }
        __syncthreads();
    }
}

// =============================================================================
// prep_kernel: wprep (8448) | conv fij (4096) | conv vec (4096) | ln (2048)
// =============================================================================
struct PrepArgs {
    const float* wsrc[11]; int wN[11]; int woff[11];
    const float* f_ij; const float* vec; const float* x;
    const float* ln_w; const float* ln_b;
};

__device__ __forceinline__ void conv_body(int i, const float* __restrict__ in,
                                          bf16* hi, bf16* lo)
{
    float4 v = ((const float4*)in)[i];
    bf16 h0 = __float2bfloat16(v.x), h1 = __float2bfloat16(v.y);
    bf16 h2 = __float2bfloat16(v.z), h3 = __float2bfloat16(v.w);
    bf16 l0 = __float2bfloat16(v.x - __bfloat162float(h0));
    bf16 l1 = __float2bfloat16(v.y - __bfloat162float(h1));
    bf16 l2 = __float2bfloat16(v.z - __bfloat162float(h2));
    bf16 l3 = __float2bfloat16(v.w - __bfloat162float(h3));
    __nv_bfloat162* hp = (__nv_bfloat162*)hi;
    __nv_bfloat162* lp = (__nv_bfloat162*)lo;
    hp[2 * i]     = __nv_bfloat162(h0, h1);
    hp[2 * i + 1] = __nv_bfloat162(h2, h3);
    lp[2 * i]     = __nv_bfloat162(l0, l1);
    lp[2 * i + 1] = __nv_bfloat162(l2, l3);
}

#define PREP_WP   8448
#define PREP_CF   4096
#define PREP_CV   4096
#define PREP_LN   2048
#define PREP_TOT  (PREP_WP + PREP_CF + PREP_CV + PREP_LN)

__global__ __launch_bounds__(256) void prep_kernel(PrepArgs P)
{
    __shared__ float red[8];
    int bx = blockIdx.x;
    const int t = threadIdx.x;

    if (bx < PREP_WP) {               // weight prep
        int w = bx / 768, n = bx % 768;
        if (n < P.wN[w]) {
            float v = P.wsrc[w][(size_t)t * P.wN[w] + n];
            bf16 h = __float2bfloat16(v);
            bf16 l = __float2bfloat16(v - __bfloat162float(h));
            size_t o = (size_t)(P.woff[w] + n) * HH + t;
            g_wh[o] = h; g_wl[o] = l;
        }
        return;
    }
    bx -= PREP_WP;
    if (bx < PREP_CF) { conv_body(bx * 256 + t, P.f_ij, g_fijh, g_fijl); return; }
    bx -= PREP_CF;
    if (bx < PREP_CV) { conv_body(bx * 256 + t, P.vec, g_vech, g_vecl); return; }
    bx -= PREP_CV;
    {                                 // LayerNorm
        int n = bx;
        float v = P.x[n * HH + t];
        float s = v;
#pragma unroll
        for (int o = 16; o; o >>= 1) s += __shfl_xor_sync(0xffffffffu, s, o);
        if ((t & 31) == 0) red[t >> 5] = s;
        __syncthreads();
        float tot = 0.f;
#pragma unroll
        for (int i = 0; i < 8; i++) tot += red[i];
        float mu = tot * (1.f / HH);
        float dv = v - mu;
        float s2 = dv * dv;
#pragma unroll
        for (int o = 16; o; o >>= 1) s2 += __shfl_xor_sync(0xffffffffu, s2, o);
        __syncthreads();
        if ((t & 31) == 0) red[t >> 5] = s2;
        __syncthreads();
        float var = 0.f;
#pragma unroll
        for (int i = 0; i < 8; i++) var += red[i];
        var *= (1.f / HH);
        float xn = dv * rsqrtf(var + 1e-5f) * P.ln_w[t] + P.ln_b[t];
        bf16 hh2 = __float2bfloat16(xn);
        g_xnh[n * HH + t] = hh2;
        g_xnl[n * HH + t] = __float2bfloat16(xn - __bfloat162float(hh2));
    }
}

// ======================= CSR build (one block) ===============================
__global__ __launch_bounds__(256) void csr_kernel(const int* __restrict__ dst)
{
    __shared__ int csr_s[BN];
    const int t = threadIdx.x;
    for (int i = t; i < BN; i += 256) csr_s[i] = 0;
    __syncthreads();
    const int4* d4 = (const int4*)dst;
#pragma unroll
    for (int i = 0; i < 16; i++) {
        int4 v = d4[t * 16 + i];
        atomicAdd(&csr_s[v.x], 1); atomicAdd(&csr_s[v.y], 1);
        atomicAdd(&csr_s[v.z], 1); atomicAdd(&csr_s[v.w], 1);
    }
    __syncthreads();
    for (int d = 1; d < BN; d <<= 1) {
        for (int i = t; i < BN / (2 * d); i += 256) {
            int idx = (i + 1) * 2 * d - 1;
            csr_s[idx] += csr_s[idx - d];
        }
        __syncthreads();
    }
    if (t == 0) { g_rowstart[BN] = csr_s[BN - 1]; csr_s[BN - 1] = 0; }
    __syncthreads();
    for (int d = BN / 2; d >= 1; d >>= 1) {
        for (int i = t; i < BN / (2 * d); i += 256) {
            int idx = (i + 1) * 2 * d - 1;
            int a = csr_s[idx - d];
            csr_s[idx - d] = csr_s[idx];
            csr_s[idx] += a;
        }
        __syncthreads();
    }
    for (int i = t; i < BN; i += 256) g_rowstart[i] = csr_s[i];
    __syncthreads();
#pragma unroll
    for (int i = 0; i < 16; i++) {
        int4 v = d4[t * 16 + i];
        int e = t * 64 + i * 4;
        int p0 = atomicAdd(&csr_s[v.x], 1); g_elist[p0] = e;
        int p1 = atomicAdd(&csr_s[v.y], 1); g_elist[p1] = e + 1;
        int p2 = atomicAdd(&csr_s[v.z], 1); g_elist[p2] = e + 2;
        int p3 = atomicAdd(&csr_s[v.w], 1); g_elist[p3] = e + 3;
    }
}

// =============================================================================
// attention (64 blocks)
// =============================================================================
__global__ __launch_bounds__(256) void attn_kernel()
{
    __shared__ float ks[64][32];
    __shared__ float vs[64][32];
    int b = blockIdx.x >> 3;
    int hd = blockIdx.x & 7;
    int i = threadIdx.x;
    float qr[32];
    const float* qrow = g_q + (size_t)(b * NN + i) * HH + hd * HD;
#pragma unroll
    for (int d = 0; d < 32; d++) qr[d] = qrow[d];
    float acc[32];
#pragma unroll
    for (int d = 0; d < 32; d++) acc[d] = 0.f;
    const float scale = rsqrtf((float)HD);

    for (int j0 = 0; j0 < NN; j0 += 64) {
        __syncthreads();
        for (int l = threadIdx.x; l < 512; l += 256) {
            int jr = l >> 3;
            int dc = (l & 7) * 4;
            size_t base = (size_t)(b * NN + j0 + jr) * HH + hd * HD + dc;
            *(float4*)&ks[jr][dc] = *(const float4*)&g_k[base];
            *(float4*)&vs[jr][dc] = *(const float4*)&g_vv[base];
        }
        __syncthreads();
        for (int j = 0; j < 64; j++) {
            float s = 0.f;
#pragma unroll
            for (int d = 0; d < 32; d++) s += qr[d] * ks[j][d];
            s = silu_f(s * scale);
#pragma unroll
            for (int d = 0; d < 32; d++) acc[d] += s * vs[j][d];
        }
    }
    size_t base = (size_t)(b * NN + i) * HH + hd * HD;
#pragma unroll
    for (int d = 0; d < 32; d++) {
        float val = acc[d] * (1.f / NN);
        bf16 h2 = __float2bfloat16(val);
        g_vath[base + d] = h2;
        g_vatl[base + d] = __float2bfloat16(val - __bfloat162float(h2));
    }
}

// =============================================================================
// wdot (EE blocks)
// =============================================================================
__global__ __launch_bounds__(256) void wdot_kernel(
    const int* __restrict__ src, const int* __restrict__ dst,
    const float* __restrict__ dij, float* __restrict__ df)
{
    __shared__ float dsh[VD];
    int e = blockIdx.x;
    int h = threadIdx.x;
    if (h < VD) dsh[h] = dij[e * VD + h];
    __syncthreads();
    int s = src[e], tt = dst[e];
    float tv[VD], sv[VD];
    float pT = 0.f, pS = 0.f;
#pragma unroll
    for (int vd = 0; vd < VD; vd++) {
        tv[vd] = g_T[(size_t)(tt * VD + vd) * HH + h];
        sv[vd] = g_S[(size_t)(s * VD + vd) * HH + h];
        pT += tv[vd] * dsh[vd];
        pS += sv[vd] * dsh[vd];
    }
    float wd = 0.f;
#pragma unroll
    for (int vd = 0; vd < VD; vd++)
        wd += (tv[vd] - pT * dsh[vd]) * (sv[vd] - pS * dsh[vd]);
    df[(size_t)e * HH + h] = g_ff[(size_t)e * HH + h] * wd;
}

// ======================= gather: x_agg + dvec (no atomics) ===================
__global__ __launch_bounds__(256) void gather_kernel(
    const float* __restrict__ s12, const float* __restrict__ vec,
    const float* __restrict__ dij, const int* __restrict__ src,
    float* __restrict__ dvec_out)
{
    int n = blockIdx.x, h = threadIdx.x;
    int beg = g_rowstart[n], end = g_rowstart[n + 1];
    float xa = 0.f;
    float dv[VD];
#pragma unroll
    for (int vd = 0; vd < VD; vd++) dv[vd] = 0.f;

    for (int i = beg; i < end; i++) {
        int e = g_elist[i];
        int s = src[e];
        float vje = __bfloat162float(g_vjh[(size_t)e * HH + h]) +
                    __bfloat162float(g_vjl[(size_t)e * HH + h]);
        xa += vje;
        float s1  = s12[(size_t)e * (2 * HH) + h];
        float s2v = s12[(size_t)e * (2 * HH) + HH + h];
#pragma unroll
        for (int vd = 0; vd < VD; vd++)
            dv[vd] += vec[(size_t)s * (VD * HH) + vd * HH + h] * s1
                    + s2v * dij[e * VD + vd];
    }
    bf16 hh = __float2bfloat16(xa);
    g_xagh[n * HH + h] = hh;
    g_xagl[n * HH + h] = __float2bfloat16(xa - __bfloat162float(hh));
#pragma unroll
    for (int vd = 0; vd < VD; vd++)
        dvec_out[(size_t)n * (VD * HH) + vd * HH + h] = dv[vd];
}

// ======================= finalize ============================================
__global__ __launch_bounds__(256) void finalize_kernel(float* __restrict__ dx,
                                                       float* __restrict__ dvec)
{
    int n = blockIdx.x, h = threadIdx.x;
    float o1 = g_o[(size_t)n * (3 * HH) + h];
    float o2 = g_o[(size_t)n * (3 * HH) + HH + h];
    float o3 = g_o[(size_t)n * (3 * HH) + 2 * HH + h];
    float vsum = 0.f;
#pragma unroll
    for (int vd = 0; vd < VD; vd++)
        vsum += g_vp[(size_t)(n * VD + vd) * (2 * HH) + h];
    dx[n * HH + h] = vsum * o2 + o3;
#pragma unroll
    for (int vd = 0; vd < VD; vd++) {
        float vec3 = g_vp[(size_t)(n * VD + vd) * (2 * HH) + HH + h];
        dvec[(size_t)n * (VD * HH) + vd * HH + h] += vec3 * o1;
    }
}

// ======================= launcher ============================================
extern "C" void kernel_launch(void* const* d_in, const int* in_sizes, int n_in,
                              void* d_out, int out_size)
{
    const float* x    = (const float*)d_in[0];
    const float* vec  = (const float*)d_in[1];
    const int*   ei   = (const int*)d_in[2];
    const float* r_ij = (const float*)d_in[3];
    const float* f_ij = (const float*)d_in[4];
    const float* d_ij = (const float*)d_in[5];
    const float* ln_w = (const float*)d_in[7];
    const float* ln_b = (const float*)d_in[8];
    const float* Wq   = (const float*)d_in[9];
    const float* Wk   = (const float*)d_in[10];
    const float* Wv   = (const float*)d_in[11];
    const float* Wao  = (const float*)d_in[12];
    const float* Wvec = (const float*)d_in[13];
    const float* Wdv  = (const float*)d_in[14];
    const float* bdv  = (const float*)d_in[15];
    const float* Ws   = (const float*)d_in[16];
    const float* bs   = (const float*)d_in[17];
    const float* Wo   = (const float*)d_in[18];
    const float* bo   = (const float*)d_in[19];
    const float* Wf   = (const float*)d_in[20];
    const float* bf   = (const float*)d_in[21];
    const float* Wsrc = (const float*)d_in[22];
    const float* Wtrg = (const float*)d_in[23];

    const int* src = ei;
    const int* dst = ei + EE;

    float* out      = (float*)d_out;
    float* out_dx   = out;
    float* out_dvec = out + (size_t)BN * HH;
    float* out_df   = out_dvec + (size_t)BN * VD * HH;

    float *p_q, *p_k, *p_vv, *p_v, *p_vp, *p_s12, *p_o, *p_T, *p_S, *p_ff, *p_zb;
    bf16 *p_xnh, *p_xnl, *p_vath, *p_vatl, *p_fijh, *p_fijl, *p_vjh, *p_vjl,
         *p_vech, *p_vecl, *p_xagh, *p_xagl, *p_wh, *p_wl;
    cudaGetSymbolAddress((void**)&p_q,    g_q);
    cudaGetSymbolAddress((void**)&p_k,    g_k);
    cudaGetSymbolAddress((void**)&p_vv,   g_vv);
    cudaGetSymbolAddress((void**)&p_v,    g_v);
    cudaGetSymbolAddress((void**)&p_vp,   g_vp);
    cudaGetSymbolAddress((void**)&p_s12,  g_s12);
    cudaGetSymbolAddress((void**)&p_o,    g_o);
    cudaGetSymbolAddress((void**)&p_T,    g_T);
    cudaGetSymbolAddress((void**)&p_S,    g_S);
    cudaGetSymbolAddress((void**)&p_ff,   g_ff);
    cudaGetSymbolAddress((void**)&p_zb,   g_zb);
    cudaGetSymbolAddress((void**)&p_xnh,  g_xnh);
    cudaGetSymbolAddress((void**)&p_xnl,  g_xnl);
    cudaGetSymbolAddress((void**)&p_vath, g_vath);
    cudaGetSymbolAddress((void**)&p_vatl, g_vatl);
    cudaGetSymbolAddress((void**)&p_fijh, g_fijh);
    cudaGetSymbolAddress((void**)&p_fijl, g_fijl);
    cudaGetSymbolAddress((void**)&p_vjh,  g_vjh);
    cudaGetSymbolAddress((void**)&p_vjl,  g_vjl);
    cudaGetSymbolAddress((void**)&p_vech, g_vech);
    cudaGetSymbolAddress((void**)&p_vecl, g_vecl);
    cudaGetSymbolAddress((void**)&p_xagh, g_xagh);
    cudaGetSymbolAddress((void**)&p_xagl, g_xagl);
    cudaGetSymbolAddress((void**)&p_wh,   g_wh);
    cudaGetSymbolAddress((void**)&p_wl,   g_wl);

    cudaFuncSetAttribute(gemm_kernel, cudaFuncAttributeMaxDynamicSharedMemorySize, MG_SMEM);

    auto WH = [&](int off) { return p_wh + (size_t)off * HH; };
    auto WL = [&](int off) { return p_wl + (size_t)off * HH; };

    // fork/join stream + events
    cudaStream_t s2;
    cudaStreamCreateWithFlags(&s2, cudaStreamNonBlocking);
    cudaEvent_t evA, evB, evC, evCSR;
    cudaEventCreateWithFlags(&evA, cudaEventDisableTiming);
    cudaEventCreateWithFlags(&evB, cudaEventDisableTiming);
    cudaEventCreateWithFlags(&evC, cudaEventDisableTiming);
    cudaEventCreateWithFlags(&evCSR, cudaEventDisableTiming);

    // ---- 1. prep (wprep + convs + ln) on stream 0 ----
    {
        PrepArgs P{};
        const float* srcs[11] = {Wq, Wk, Wv, Wao, Wdv, Wf, Ws, Wvec, Wo, Wtrg, Wsrc};
        int ns[11]   = {256, 256, 256, 256, 256, 256, 512, 512, 768, 256, 256};
        int offs[11] = {OFF_WQ, OFF_WK, OFF_WV, OFF_WAO, OFF_WDV, OFF_WF,
                        OFF_WS, OFF_WVEC, OFF_WO, OFF_WTRG, OFF_WSRC};
        for (int i = 0; i < 11; i++) { P.wsrc[i] = srcs[i]; P.wN[i] = ns[i]; P.woff[i] = offs[i]; }
        P.f_ij = f_ij; P.vec = vec; P.x = x; P.ln_w = ln_w; P.ln_b = ln_b;
        prep_kernel<<<PREP_TOT, 256>>>(P);
    }

    // ---- fork: stream2 ----
    cudaEventRecord(evA, 0);
    cudaStreamWaitEvent(s2, evA, 0);

    // stream2: CSR (1 block, independent of prep outputs but ordered is fine)
    csr_kernel<<<1, 256, 0, s2>>>(dst);
    cudaEventRecord(evCSR, s2);

    // stream2: ff/vp/T/S (4 jobs, 2560 tiles) persistent on 148 CTAs (1/SM)
    {
        GArgs A{};
        A.njobs = 4; A.mode = 0; A.totalTiles = 2560;
        A.jobs[0] = {p_fijh, p_fijl, WH(OFF_WF),   WL(OFF_WF),   bf,   p_ff, HH,     4, 1, 0};
        A.jobs[1] = {p_vech, p_vecl, WH(OFF_WVEC), WL(OFF_WVEC), p_zb, p_vp, 2 * HH, 8, 0, 512};
        A.jobs[2] = {p_vech, p_vecl, WH(OFF_WTRG), WL(OFF_WTRG), p_zb, p_T,  HH,     4, 0, 1536};
        A.jobs[3] = {p_vech, p_vecl, WH(OFF_WSRC), WL(OFF_WSRC), p_zb, p_S,  HH,     4, 0, 2048};
        gemm_kernel<<<148, 256, MG_SMEM, s2>>>(A);
    }
    cudaEventRecord(evB, s2);                       // ff/vp/T/S ready
    wdot_kernel<<<EE, 256, 0, s2>>>(src, dst, d_ij, out_df);
    cudaEventRecord(evC, s2);                       // branch done

    // ---- stream0 critical chain ----
    // qkv (3 jobs, 192 tiles)
    {
        GArgs A{};
        A.njobs = 3; A.mode = 0; A.totalTiles = 192;
        A.jobs[0] = {p_xnh, p_xnl, WH(OFF_WQ), WL(OFF_WQ), p_zb, p_q,  HH, 4, 0, 0};
        A.jobs[1] = {p_xnh, p_xnl, WH(OFF_WK), WL(OFF_WK), p_zb, p_k,  HH, 4, 0, 64};
        A.jobs[2] = {p_xnh, p_xnl, WH(OFF_WV), WL(OFF_WV), p_zb, p_vv, HH, 4, 0, 128};
        gemm_kernel<<<192, 256, MG_SMEM>>>(A);
    }

    // attention
    attn_kernel<<<64, 256>>>();

    // v = vatt @ Wao (64 tiles)
    {
        GArgs A{};
        A.njobs = 1; A.mode = 0; A.totalTiles = 64;
        A.jobs[0] = {p_vath, p_vatl, WH(OFF_WAO), WL(OFF_WAO), p_zb, p_v, HH, 4, 0, 0};
        gemm_kernel<<<64, 256, MG_SMEM>>>(A);
    }

    // vj = silu(f_ij @ Wdv + bdv)*cut*v[src] -> bf16 hi/lo (512 tiles)
    {
        GArgs A{};
        A.njobs = 1; A.mode = 1; A.totalTiles = 512;
        A.jobs[0] = {p_fijh, p_fijl, WH(OFF_WDV), WL(OFF_WDV), bdv, nullptr, HH, 4, 0, 0};
        A.vsrc = p_v; A.srcidx = src; A.rij = r_ij; A.Oh = p_vjh; A.Ol = p_vjl;
        gemm_kernel<<<512, 256, MG_SMEM>>>(A);
    }

    // s12 = silu(v_j @ Ws + bs) (1024 tiles)
    {
        GArgs A{};
        A.njobs = 1; A.mode = 0; A.totalTiles = 1024;
        A.jobs[0] = {p_vjh, p_vjl, WH(OFF_WS), WL(OFF_WS), bs, p_s12, 2 * HH, 8, 1, 0};
        gemm_kernel<<<1024, 256, MG_SMEM>>>(A);
    }

    // gather (needs CSR)
    cudaStreamWaitEvent(0, evCSR, 0);
    gather_kernel<<<BN, 256>>>(p_s12, vec, d_ij, src, out_dvec);

    // o = x_agg @ Wo + bo (192 tiles)
    {
        GArgs A{};
        A.njobs = 1; A.mode = 0; A.totalTiles = 192;
        A.jobs[0] = {p_xagh, p_xagl, WH(OFF_WO), WL(OFF_WO), bo, p_o, 3 * HH, 12, 0, 0};
        gemm_kernel<<<192, 256, MG_SMEM>>>(A);
    }

    // finalize needs vp from stream2 branch
    cudaStreamWaitEvent(0, evB, 0);
    finalize_kernel<<<BN, 256>>>(out_dx, out_dvec);

    // join branch (wdot) before returning
    cudaStreamWaitEvent(0, evC, 0);
}

// round 13
// speedup vs baseline: 1.2110x; 1.0064x over previous
#include <cuda_runtime.h>
#include <cuda_bf16.h>
#include <cstdint>

// Problem constants
#define BB 8
#define NN 256
#define BN 2048          // BB*NN
#define EE 16384
#define HH 256
#define NHD 8
#define HD 32
#define VD 8

typedef __nv_bfloat16 bf16;

// ---------------- fp32 scratch ------------------------------------------------
__device__ float g_q   [BN*HH];
__device__ float g_k   [BN*HH];
__device__ float g_vv  [BN*HH];
__device__ float g_v   [BN*HH];
__device__ float g_vp  [BN*VD*2*HH];
__device__ float g_s12 [EE*2*HH];
__device__ float g_o   [BN*3*HH];
__device__ float g_T   [BN*VD*HH];
__device__ float g_S   [BN*VD*HH];
__device__ float g_ff  [EE*HH];
__device__ float g_zb  [3*HH];          // zero bias (static zero-init)

// ---------------- bf16 hi/lo scratch -----------------------------------------
__device__ bf16 g_xnh [BN*HH],    g_xnl [BN*HH];
__device__ bf16 g_vath[BN*HH],    g_vatl[BN*HH];
__device__ bf16 g_fijh[EE*HH],    g_fijl[EE*HH];
__device__ bf16 g_vjh [EE*HH],    g_vjl [EE*HH];
__device__ bf16 g_vech[BN*VD*HH], g_vecl[BN*VD*HH];
__device__ bf16 g_xagh[BN*HH],    g_xagl[BN*HH];
#define WROWS 3840
__device__ bf16 g_wh[WROWS*HH], g_wl[WROWS*HH];

// ---------------- CSR scratch -------------------------------------------------
__device__ int g_rowstart[BN + 1];
__device__ int g_elist[EE];

// weight row offsets within g_wh/g_wl
#define OFF_WQ   0
#define OFF_WK   256
#define OFF_WV   512
#define OFF_WAO  768
#define OFF_WDV  1024
#define OFF_WF   1280
#define OFF_WS   1536
#define OFF_WVEC 2048
#define OFF_WO   2560
#define OFF_WTRG 3328
#define OFF_WSRC 3584

__device__ __forceinline__ float silu_f(float x) { return x / (1.f + __expf(-x)); }
__device__ __forceinline__ float cut_f(float rr) {
    return (rr < 5.f) ? 0.5f * (cosf(rr * 0.6283185307179586f) + 1.f) : 0.f;
}

__device__ __forceinline__ uint32_t smem_u32(const void* p) {
    uint32_t a;
    asm("{ .reg .u64 t; cvta.to.shared.u64 t, %1; cvt.u32.u64 %0, t; }" : "=r"(a) : "l"(p));
    return a;
}

// ---------------- mma.sync / ldmatrix / cp.async wrappers --------------------
__device__ __forceinline__ void ldsm4(uint32_t* r, uint32_t addr) {
    asm volatile("ldmatrix.sync.aligned.m8n8.x4.shared.b16 {%0,%1,%2,%3}, [%4];"
                 : "=r"(r[0]), "=r"(r[1]), "=r"(r[2]), "=r"(r[3]) : "r"(addr));
}
__device__ __forceinline__ void mma_bf16(float* d, const uint32_t* a, const uint32_t* b) {
    asm volatile("mma.sync.aligned.m16n8k16.row.col.f32.bf16.bf16.f32 "
                 "{%0,%1,%2,%3}, {%4,%5,%6,%7}, {%8,%9}, {%0,%1,%2,%3};"
                 : "+f"(d[0]), "+f"(d[1]), "+f"(d[2]), "+f"(d[3])
                 : "r"(a[0]), "r"(a[1]), "r"(a[2]), "r"(a[3]), "r"(b[0]), "r"(b[1]));
}
#define CP_COMMIT() asm volatile("cp.async.commit_group;" ::: "memory")

// =============================================================================
// Unified job-table GEMM, 128x64 tiles (96KB smem -> 2 CTAs/SM), persistent
// grid-stride over totalTiles.
// Mode 0: C = [silu](A@W^T + bias) fp32.
// Mode 1: vj epilogue silu(acc+bias)*cut(r[row])*v[src[row]][col] -> bf16 hi/lo.
// =============================================================================
struct GJob {
    const bf16 *Ah, *Al, *Bh, *Bl;
    const float* bias;
    float* C;
    int Nfull, colTiles, silu, tileOfs;
};
struct GArgs {
    GJob jobs[7];
    int njobs;
    int mode;
    int totalTiles;
    const float* vsrc; const int* srcidx; const float* rij;
    bf16 *Oh, *Ol;
};

#define CHUNK_BYTES 49152
#define MG_SMEM (2 * CHUNK_BYTES)   // 96 KB

__device__ __forceinline__ void cp_tileA(uint32_t dst_s, const bf16* __restrict__ src,
                                         int rowbase, int kc, int tid)
{
    const char* g = (const char*)(src + (size_t)rowbase * HH + kc * 64);
#pragma unroll
    for (int it = 0; it < 4; it++) {
        int u   = tid + it * 256;       // 1024 units: 128 rows x 8
        int row = u >> 3;
        int ui  = u & 7;
        uint32_t off = row * 128 + ui * 16;
        off ^= (off >> 3) & 0x70;
        asm volatile("cp.async.cg.shared.global [%0], [%1], 16;"
                     :: "r"(dst_s + off), "l"(g + (size_t)row * 512 + ui * 16));
    }
}
__device__ __forceinline__ void cp_tileB(uint32_t dst_s, const bf16* __restrict__ src,
                                         int rowbase, int kc, int tid)
{
    const char* g = (const char*)(src + (size_t)rowbase * HH + kc * 64);
#pragma unroll
    for (int it = 0; it < 2; it++) {
        int u   = tid + it * 256;       // 512 units: 64 rows x 8
        int row = u >> 3;
        int ui  = u & 7;
        uint32_t off = row * 128 + ui * 16;
        off ^= (off >> 3) & 0x70;
        asm volatile("cp.async.cg.shared.global [%0], [%1], 16;"
                     :: "r"(dst_s + off), "l"(g + (size_t)row * 512 + ui * 16));
    }
}

__device__ __forceinline__ void cp_chunk(uint32_t sbase,
    const bf16* Ah, const bf16* Al, const bf16* Bh, const bf16* Bl,
    int rowA, int colB, int kc, int tid)
{
    cp_tileA(sbase,         Ah, rowA, kc, tid);
    cp_tileA(sbase + 16384, Al, rowA, kc, tid);
    cp_tileB(sbase + 32768, Bh, colB, kc, tid);
    cp_tileB(sbase + 40960, Bl, colB, kc, tid);
}

__global__ __launch_bounds__(256) void gemm_kernel(GArgs P)
{
    extern __shared__ uint8_t smem[];
    const int tid = threadIdx.x, wid = tid >> 5, lane = tid & 31;
    const int wr = wid >> 1, wc = wid & 1;   // warp tile: 32 rows x 32 cols

    uint32_t aoff[2], boff[2];
#pragma unroll
    for (int i = 0; i < 2; i++)
        aoff[i] = (uint32_t)((wr * 32 + i * 16 + (lane & 15)) * 128 + (lane >> 4) * 16);
    {
        int grp = lane >> 3, lr = lane & 7;
#pragma unroll
        for (int j2 = 0; j2 < 2; j2++)
            boff[j2] = (uint32_t)((wc * 32 + j2 * 16 + (grp >> 1) * 8 + lr) * 128
                                  + (grp & 1) * 16);
    }
    const uint32_t sb = smem_u32(smem);
    const int r0 = lane >> 2, c0 = (lane & 3) * 2;

    for (int tile = blockIdx.x; tile < P.totalTiles; tile += gridDim.x) {

        int j = 0;
#pragma unroll
        for (int jj = 1; jj < 7; jj++)
            if (jj < P.njobs && tile >= P.jobs[jj].tileOfs) j = jj;
        const GJob job = P.jobs[j];
        const int local = tile - job.tileOfs;
        const int rowA = (local / job.colTiles) * 128;
        const int colB = (local % job.colTiles) * 64;

        const bf16* __restrict__ Ah = job.Ah;
        const bf16* __restrict__ Al = job.Al;
        const bf16* __restrict__ Bh = job.Bh;
        const bf16* __restrict__ Bl = job.Bl;

        float acc[2][4][4];
#pragma unroll
        for (int i = 0; i < 2; i++)
#pragma unroll
            for (int jj = 0; jj < 4; jj++)
#pragma unroll
                for (int r = 0; r < 4; r++) acc[i][jj][r] = 0.f;

        cp_chunk(sb,               Ah, Al, Bh, Bl, rowA, colB, 0, tid); CP_COMMIT();
        cp_chunk(sb + CHUNK_BYTES, Ah, Al, Bh, Bl, rowA, colB, 1, tid); CP_COMMIT();

        int buf = 0;
        for (int kc = 0; kc < 4; kc++) {
            if (kc < 3) asm volatile("cp.async.wait_group 1;" ::: "memory");
            else        asm volatile("cp.async.wait_group 0;" ::: "memory");
            __syncthreads();
            const uint32_t base = sb + buf * CHUNK_BYTES;
#pragma unroll
            for (int ks = 0; ks < 4; ks++) {
                const uint32_t kb = ks * 32;
                uint32_t ahf[2][4], alf[2][4], bhf[2][4], blf[2][4];
#pragma unroll
                for (int i = 0; i < 2; i++) {
                    uint32_t o = aoff[i] + kb; o ^= (o >> 3) & 0x70;
                    ldsm4(ahf[i], base + o);
                    ldsm4(alf[i], base + 16384 + o);
                }
#pragma unroll
                for (int j2 = 0; j2 < 2; j2++) {
                    uint32_t o = boff[j2] + kb; o ^= (o >> 3) & 0x70;
                    ldsm4(bhf[j2], base + 32768 + o);
                    ldsm4(blf[j2], base + 40960 + o);
                }
                // Pass 1: all 8 independent Ahi*Bhi
#pragma unroll
                for (int i = 0; i < 2; i++)
#pragma unroll
                    for (int jj = 0; jj < 4; jj++)
                        mma_bf16(acc[i][jj], ahf[i], &bhf[jj >> 1][(jj & 1) * 2]);
                // Pass 2: all 8 independent Ahi*Blo
#pragma unroll
                for (int i = 0; i < 2; i++)
#pragma unroll
                    for (int jj = 0; jj < 4; jj++)
                        mma_bf16(acc[i][jj], ahf[i], &blf[jj >> 1][(jj & 1) * 2]);
                // Pass 3: all 8 independent Alo*Bhi
#pragma unroll
                for (int i = 0; i < 2; i++)
#pragma unroll
                    for (int jj = 0; jj < 4; jj++)
                        mma_bf16(acc[i][jj], alf[i], &bhf[jj >> 1][(jj & 1) * 2]);
            }
            __syncthreads();
            if (kc + 2 <= 3) {
                cp_chunk(sb + buf * CHUNK_BYTES, Ah, Al, Bh, Bl, rowA, colB, kc + 2, tid);
                CP_COMMIT();
            }
            buf ^= 1;
        }

        const float* bias = job.bias;

        if (P.mode == 1) {
            __nv_bfloat162* OH = (__nv_bfloat162*)P.Oh;
            __nv_bfloat162* OL = (__nv_bfloat162*)P.Ol;
#pragma unroll
            for (int i = 0; i < 2; i++) {
                const int row0 = rowA + wr * 32 + i * 16 + r0;
                const int row1 = row0 + 8;
                const int s0 = P.srcidx[row0], s1i = P.srcidx[row1];
                const float cut0 = cut_f(P.rij[row0]);
                const float cut1 = cut_f(P.rij[row1]);
#pragma unroll
                for (int jj = 0; jj < 4; jj++) {
                    const int gcol = colB + wc * 32 + jj * 8 + c0;
                    const float b0 = bias[gcol], b1 = bias[gcol + 1];
                    float v0 = silu_f(acc[i][jj][0] + b0) * cut0 * P.vsrc[(size_t)s0 * HH + gcol];
                    float v1 = silu_f(acc[i][jj][1] + b1) * cut0 * P.vsrc[(size_t)s0 * HH + gcol + 1];
                    float v2 = silu_f(acc[i][jj][2] + b0) * cut1 * P.vsrc[(size_t)s1i * HH + gcol];
                    float v3 = silu_f(acc[i][jj][3] + b1) * cut1 * P.vsrc[(size_t)s1i * HH + gcol + 1];
                    bf16 h0 = __float2bfloat16(v0), h1 = __float2bfloat16(v1);
                    bf16 h2 = __float2bfloat16(v2), h3 = __float2bfloat16(v3);
                    bf16 l0 = __float2bfloat16(v0 - __bfloat162float(h0));
                    bf16 l1 = __float2bfloat16(v1 - __bfloat162float(h1));
                    bf16 l2 = __float2bfloat16(v2 - __bfloat162float(h2));
                    bf16 l3 = __float2bfloat16(v3 - __bfloat162float(h3));
                    OH[(size_t)row0 * 128 + (gcol >> 1)] = __nv_bfloat162(h0, h1);
                    OL[(size_t)row0 * 128 + (gcol >> 1)] = __nv_bfloat162(l0, l1);
                    OH[(size_t)row1 * 128 + (gcol >> 1)] = __nv_bfloat162(h2, h3);
                    OL[(size_t)row1 * 128 + (gcol >> 1)] = __nv_bfloat162(l2, l3);
                }
            }
        } else {
            float* __restrict__ C = job.C;
            const int Nfull = job.Nfull;
            const int do_silu = job.silu;
#pragma unroll
            for (int i = 0; i < 2; i++) {
                const int grow = rowA + wr * 32 + i * 16 + r0;
#pragma unroll
                for (int jj = 0; jj < 4; jj++) {
                    const int gcol = colB + wc * 32 + jj * 8 + c0;
                    float b0 = bias[gcol], b1 = bias[gcol + 1];
                    float v0 = acc[i][jj][0] + b0, v1 = acc[i][jj][1] + b1;
                    float v2 = acc[i][jj][2] + b0, v3 = acc[i][jj][3] + b1;
                    if (do_silu) {
                        v0 = silu_f(v0); v1 = silu_f(v1); v2 = silu_f(v2); v3 = silu_f(v3);
                    }
                    *(float2*)(C + (size_t)grow * Nfull + gcol)       = make_float2(v0, v1);
                    *(float2*)(C + (size_t)(grow + 8) * Nfull + gcol) = make_float2(v2, v3);
                }
            }
        }
        __syncthreads();
    }
}

// =============================================================================
// prep_kernel: wprep (8448) | conv fij (4096) | conv vec (4096) | ln (2048)
// =============================================================================
struct PrepArgs {
    const float* wsrc[11]; int wN[11]; int woff[11];
    const float* f_ij; const float* vec; const float* x;
    const float* ln_w; const float* ln_b;
};

__device__ __forceinline__ void conv_body(int i, const float* __restrict__ in,
                                          bf16* hi, bf16* lo)
{
    float4 v = ((const float4*)in)[i];
    bf16 h0 = __float2bfloat16(v.x), h1 = __float2bfloat16(v.y);
    bf16 h2 = __float2bfloat16(v.z), h3 = __float2bfloat16(v.w);
    bf16 l0 = __float2bfloat16(v.x - __bfloat162float(h0));
    bf16 l1 = __float2bfloat16(v.y - __bfloat162float(h1));
    bf16 l2 = __float2bfloat16(v.z - __bfloat162float(h2));
    bf16 l3 = __float2bfloat16(v.w - __bfloat162float(h3));
    __nv_bfloat162* hp = (__nv_bfloat162*)hi;
    __nv_bfloat162* lp = (__nv_bfloat162*)lo;
    hp[2 * i]     = __nv_bfloat162(h0, h1);
    hp[2 * i + 1] = __nv_bfloat162(h2, h3);
    lp[2 * i]     = __nv_bfloat162(l0, l1);
    lp[2 * i + 1] = __nv_bfloat162(l2, l3);
}

#define PREP_WP   8448
#define PREP_CF   4096
#define PREP_CV   4096
#define PREP_LN   2048
#define PREP_TOT  (PREP_WP + PREP_CF + PREP_CV + PREP_LN)

__global__ __launch_bounds__(256) void prep_kernel(PrepArgs P)
{
    __shared__ float red[8];
    int bx = blockIdx.x;
    const int t = threadIdx.x;

    if (bx < PREP_WP) {               // weight prep
        int w = bx / 768, n = bx % 768;
        if (n < P.wN[w]) {
            float v = P.wsrc[w][(size_t)t * P.wN[w] + n];
            bf16 h = __float2bfloat16(v);
            bf16 l = __float2bfloat16(v - __bfloat162float(h));
            size_t o = (size_t)(P.woff[w] + n) * HH + t;
            g_wh[o] = h; g_wl[o] = l;
        }
        return;
    }
    bx -= PREP_WP;
    if (bx < PREP_CF) { conv_body(bx * 256 + t, P.f_ij, g_fijh, g_fijl); return; }
    bx -= PREP_CF;
    if (bx < PREP_CV) { conv_body(bx * 256 + t, P.vec, g_vech, g_vecl); return; }
    bx -= PREP_CV;
    {                                 // LayerNorm
        int n = bx;
        float v = P.x[n * HH + t];
        float s = v;
#pragma unroll
        for (int o = 16; o; o >>= 1) s += __shfl_xor_sync(0xffffffffu, s, o);
        if ((t & 31) == 0) red[t >> 5] = s;
        __syncthreads();
        float tot = 0.f;
#pragma unroll
        for (int i = 0; i < 8; i++) tot += red[i];
        float mu = tot * (1.f / HH);
        float dv = v - mu;
        float s2 = dv * dv;
#pragma unroll
        for (int o = 16; o; o >>= 1) s2 += __shfl_xor_sync(0xffffffffu, s2, o);
        __syncthreads();
        if ((t & 31) == 0) red[t >> 5] = s2;
        __syncthreads();
        float var = 0.f;
#pragma unroll
        for (int i = 0; i < 8; i++) var += red[i];
        var *= (1.f / HH);
        float xn = dv * rsqrtf(var + 1e-5f) * P.ln_w[t] + P.ln_b[t];
        bf16 hh2 = __float2bfloat16(xn);
        g_xnh[n * HH + t] = hh2;
        g_xnl[n * HH + t] = __float2bfloat16(xn - __bfloat162float(hh2));
    }
}

// ======================= CSR build (one block) ===============================
__global__ __launch_bounds__(256) void csr_kernel(const int* __restrict__ dst)
{
    __shared__ int csr_s[BN];
    const int t = threadIdx.x;
    for (int i = t; i < BN; i += 256) csr_s[i] = 0;
    __syncthreads();
    const int4* d4 = (const int4*)dst;
#pragma unroll
    for (int i = 0; i < 16; i++) {
        int4 v = d4[t * 16 + i];
        atomicAdd(&csr_s[v.x], 1); atomicAdd(&csr_s[v.y], 1);
        atomicAdd(&csr_s[v.z], 1); atomicAdd(&csr_s[v.w], 1);
    }
    __syncthreads();
    for (int d = 1; d < BN; d <<= 1) {
        for (int i = t; i < BN / (2 * d); i += 256) {
            int idx = (i + 1) * 2 * d - 1;
            csr_s[idx] += csr_s[idx - d];
        }
        __syncthreads();
    }
    if (t == 0) { g_rowstart[BN] = csr_s[BN - 1]; csr_s[BN - 1] = 0; }
    __syncthreads();
    for (int d = BN / 2; d >= 1; d >>= 1) {
        for (int i = t; i < BN / (2 * d); i += 256) {
            int idx = (i + 1) * 2 * d - 1;
            int a = csr_s[idx - d];
            csr_s[idx - d] = csr_s[idx];
            csr_s[idx] += a;
        }
        __syncthreads();
    }
    for (int i = t; i < BN; i += 256) g_rowstart[i] = csr_s[i];
    __syncthreads();
#pragma unroll
    for (int i = 0; i < 16; i++) {
        int4 v = d4[t * 16 + i];
        int e = t * 64 + i * 4;
        int p0 = atomicAdd(&csr_s[v.x], 1); g_elist[p0] = e;
        int p1 = atomicAdd(&csr_s[v.y], 1); g_elist[p1] = e + 1;
        int p2 = atomicAdd(&csr_s[v.z], 1); g_elist[p2] = e + 2;
        int p3 = atomicAdd(&csr_s[v.w], 1); g_elist[p3] = e + 3;
    }
}

// =============================================================================
// attention (64 blocks)
// =============================================================================
__global__ __launch_bounds__(256) void attn_kernel()
{
    __shared__ float ks[64][32];
    __shared__ float vs[64][32];
    int b = blockIdx.x >> 3;
    int hd = blockIdx.x & 7;
    int i = threadIdx.x;
    float qr[32];
    const float* qrow = g_q + (size_t)(b * NN + i) * HH + hd * HD;
#pragma unroll
    for (int d = 0; d < 32; d++) qr[d] = qrow[d];
    float acc[32];
#pragma unroll
    for (int d = 0; d < 32; d++) acc[d] = 0.f;
    const float scale = rsqrtf((float)HD);

    for (int j0 = 0; j0 < NN; j0 += 64) {
        __syncthreads();
        for (int l = threadIdx.x; l < 512; l += 256) {
            int jr = l >> 3;
            int dc = (l & 7) * 4;
            size_t base = (size_t)(b * NN + j0 + jr) * HH + hd * HD + dc;
            *(float4*)&ks[jr][dc] = *(const float4*)&g_k[base];
            *(float4*)&vs[jr][dc] = *(const float4*)&g_vv[base];
        }
        __syncthreads();
        for (int j = 0; j < 64; j++) {
            float s = 0.f;
#pragma unroll
            for (int d = 0; d < 32; d++) s += qr[d] * ks[j][d];
            s = silu_f(s * scale);
#pragma unroll
            for (int d = 0; d < 32; d++) acc[d] += s * vs[j][d];
        }
    }
    size_t base = (size_t)(b * NN + i) * HH + hd * HD;
#pragma unroll
    for (int d = 0; d < 32; d++) {
        float val = acc[d] * (1.f / NN);
        bf16 h2 = __float2bfloat16(val);
        g_vath[base + d] = h2;
        g_vatl[base + d] = __float2bfloat16(val - __bfloat162float(h2));
    }
}

// =============================================================================
// wdot: persistent 1024 blocks; wd = dot(tv,sv) - pT*pS  (||d||=1 identity)
// =============================================================================
#define WDOT_GRID 1024
__global__ __launch_bounds__(256) void wdot_kernel(
    const int* __restrict__ src, const int* __restrict__ dst,
    const float* __restrict__ dij, float* __restrict__ df)
{
    const int h = threadIdx.x;
    for (int e = blockIdx.x; e < EE; e += WDOT_GRID) {
        int s = src[e], tt = dst[e];
        float dot = 0.f, pT = 0.f, pS = 0.f;
#pragma unroll
        for (int vd = 0; vd < VD; vd++) {
            float d  = __ldg(&dij[e * VD + vd]);
            float tv = g_T[(size_t)(tt * VD + vd) * HH + h];
            float sv = g_S[(size_t)(s * VD + vd) * HH + h];
            dot += tv * sv;
            pT  += tv * d;
            pS  += sv * d;
        }
        df[(size_t)e * HH + h] = g_ff[(size_t)e * HH + h] * (dot - pT * pS);
    }
}

// ======================= gather: x_agg + dvec (no atomics) ===================
__global__ __launch_bounds__(256) void gather_kernel(
    const float* __restrict__ s12, const float* __restrict__ vec,
    const float* __restrict__ dij, const int* __restrict__ src,
    float* __restrict__ dvec_out)
{
    int n = blockIdx.x, h = threadIdx.x;
    int beg = g_rowstart[n], end = g_rowstart[n + 1];
    float xa = 0.f;
    float dv[VD];
#pragma unroll
    for (int vd = 0; vd < VD; vd++) dv[vd] = 0.f;

    for (int i = beg; i < end; i++) {
        int e = g_elist[i];
        int s = src[e];
        float vje = __bfloat162float(g_vjh[(size_t)e * HH + h]) +
                    __bfloat162float(g_vjl[(size_t)e * HH + h]);
        xa += vje;
        float s1  = s12[(size_t)e * (2 * HH) + h];
        float s2v = s12[(size_t)e * (2 * HH) + HH + h];
#pragma unroll
        for (int vd = 0; vd < VD; vd++)
            dv[vd] += vec[(size_t)s * (VD * HH) + vd * HH + h] * s1
                    + s2v * dij[e * VD + vd];
    }
    bf16 hh = __float2bfloat16(xa);
    g_xagh[n * HH + h] = hh;
    g_xagl[n * HH + h] = __float2bfloat16(xa - __bfloat162float(hh));
#pragma unroll
    for (int vd = 0; vd < VD; vd++)
        dvec_out[(size_t)n * (VD * HH) + vd * HH + h] = dv[vd];
}

// ======================= finalize ============================================
__global__ __launch_bounds__(256) void finalize_kernel(float* __restrict__ dx,
                                                       float* __restrict__ dvec)
{
    int n = blockIdx.x, h = threadIdx.x;
    float o1 = g_o[(size_t)n * (3 * HH) + h];
    float o2 = g_o[(size_t)n * (3 * HH) + HH + h];
    float o3 = g_o[(size_t)n * (3 * HH) + 2 * HH + h];
    float vsum = 0.f;
#pragma unroll
    for (int vd = 0; vd < VD; vd++)
        vsum += g_vp[(size_t)(n * VD + vd) * (2 * HH) + h];
    dx[n * HH + h] = vsum * o2 + o3;
#pragma unroll
    for (int vd = 0; vd < VD; vd++) {
        float vec3 = g_vp[(size_t)(n * VD + vd) * (2 * HH) + HH + h];
        dvec[(size_t)n * (VD * HH) + vd * HH + h] += vec3 * o1;
    }
}

// ======================= launcher ============================================
extern "C" void kernel_launch(void* const* d_in, const int* in_sizes, int n_in,
                              void* d_out, int out_size)
{
    const float* x    = (const float*)d_in[0];
    const float* vec  = (const float*)d_in[1];
    const int*   ei   = (const int*)d_in[2];
    const float* r_ij = (const float*)d_in[3];
    const float* f_ij = (const float*)d_in[4];
    const float* d_ij = (const float*)d_in[5];
    const float* ln_w = (const float*)d_in[7];
    const float* ln_b = (const float*)d_in[8];
    const float* Wq   = (const float*)d_in[9];
    const float* Wk   = (const float*)d_in[10];
    const float* Wv   = (const float*)d_in[11];
    const float* Wao  = (const float*)d_in[12];
    const float* Wvec = (const float*)d_in[13];
    const float* Wdv  = (const float*)d_in[14];
    const float* bdv  = (const float*)d_in[15];
    const float* Ws   = (const float*)d_in[16];
    const float* bs   = (const float*)d_in[17];
    const float* Wo   = (const float*)d_in[18];
    const float* bo   = (const float*)d_in[19];
    const float* Wf   = (const float*)d_in[20];
    const float* bf   = (const float*)d_in[21];
    const float* Wsrc = (const float*)d_in[22];
    const float* Wtrg = (const float*)d_in[23];

    const int* src = ei;
    const int* dst = ei + EE;

    float* out      = (float*)d_out;
    float* out_dx   = out;
    float* out_dvec = out + (size_t)BN * HH;
    float* out_df   = out_dvec + (size_t)BN * VD * HH;

    float *p_q, *p_k, *p_vv, *p_v, *p_vp, *p_s12, *p_o, *p_T, *p_S, *p_ff, *p_zb;
    bf16 *p_xnh, *p_xnl, *p_vath, *p_vatl, *p_fijh, *p_fijl, *p_vjh, *p_vjl,
         *p_vech, *p_vecl, *p_xagh, *p_xagl, *p_wh, *p_wl;
    cudaGetSymbolAddress((void**)&p_q,    g_q);
    cudaGetSymbolAddress((void**)&p_k,    g_k);
    cudaGetSymbolAddress((void**)&p_vv,   g_vv);
    cudaGetSymbolAddress((void**)&p_v,    g_v);
    cudaGetSymbolAddress((void**)&p_vp,   g_vp);
    cudaGetSymbolAddress((void**)&p_s12,  g_s12);
    cudaGetSymbolAddress((void**)&p_o,    g_o);
    cudaGetSymbolAddress((void**)&p_T,    g_T);
    cudaGetSymbolAddress((void**)&p_S,    g_S);
    cudaGetSymbolAddress((void**)&p_ff,   g_ff);
    cudaGetSymbolAddress((void**)&p_zb,   g_zb);
    cudaGetSymbolAddress((void**)&p_xnh,  g_xnh);
    cudaGetSymbolAddress((void**)&p_xnl,  g_xnl);
    cudaGetSymbolAddress((void**)&p_vath, g_vath);
    cudaGetSymbolAddress((void**)&p_vatl, g_vatl);
    cudaGetSymbolAddress((void**)&p_fijh, g_fijh);
    cudaGetSymbolAddress((void**)&p_fijl, g_fijl);
    cudaGetSymbolAddress((void**)&p_vjh,  g_vjh);
    cudaGetSymbolAddress((void**)&p_vjl,  g_vjl);
    cudaGetSymbolAddress((void**)&p_vech, g_vech);
    cudaGetSymbolAddress((void**)&p_vecl, g_vecl);
    cudaGetSymbolAddress((void**)&p_xagh, g_xagh);
    cudaGetSymbolAddress((void**)&p_xagl, g_xagl);
    cudaGetSymbolAddress((void**)&p_wh,   g_wh);
    cudaGetSymbolAddress((void**)&p_wl,   g_wl);

    cudaFuncSetAttribute(gemm_kernel, cudaFuncAttributeMaxDynamicSharedMemorySize, MG_SMEM);

    auto WH = [&](int off) { return p_wh + (size_t)off * HH; };
    auto WL = [&](int off) { return p_wl + (size_t)off * HH; };

    // ONE extra stream (round-10 proven-clean topology) + events
    cudaStream_t s2;
    cudaStreamCreateWithFlags(&s2, cudaStreamNonBlocking);
    cudaEvent_t evA, evB, evC, evCSR;
    cudaEventCreateWithFlags(&evA, cudaEventDisableTiming);
    cudaEventCreateWithFlags(&evB, cudaEventDisableTiming);
    cudaEventCreateWithFlags(&evC, cudaEventDisableTiming);
    cudaEventCreateWithFlags(&evCSR, cudaEventDisableTiming);

    // ---- 1. prep (wprep + convs + ln) on stream 0 ----
    {
        PrepArgs P{};
        const float* srcs[11] = {Wq, Wk, Wv, Wao, Wdv, Wf, Ws, Wvec, Wo, Wtrg, Wsrc};
        int ns[11]   = {256, 256, 256, 256, 256, 256, 512, 512, 768, 256, 256};
        int offs[11] = {OFF_WQ, OFF_WK, OFF_WV, OFF_WAO, OFF_WDV, OFF_WF,
                        OFF_WS, OFF_WVEC, OFF_WO, OFF_WTRG, OFF_WSRC};
        for (int i = 0; i < 11; i++) { P.wsrc[i] = srcs[i]; P.wN[i] = ns[i]; P.woff[i] = offs[i]; }
        P.f_ij = f_ij; P.vec = vec; P.x = x; P.ln_w = ln_w; P.ln_b = ln_b;
        prep_kernel<<<PREP_TOT, 256>>>(P);
    }

    // ---- fork: branch on s2 ----
    cudaEventRecord(evA, 0);
    cudaStreamWaitEvent(s2, evA, 0);

    // s2: CSR, then ff/vp/T/S persistent 148 CTAs, then wdot
    csr_kernel<<<1, 256, 0, s2>>>(dst);
    cudaEventRecord(evCSR, s2);
    {
        GArgs A{};
        A.njobs = 4; A.mode = 0; A.totalTiles = 2560;
        A.jobs[0] = {p_fijh, p_fijl, WH(OFF_WF),   WL(OFF_WF),   bf,   p_ff, HH,     4, 1, 0};
        A.jobs[1] = {p_vech, p_vecl, WH(OFF_WVEC), WL(OFF_WVEC), p_zb, p_vp, 2 * HH, 8, 0, 512};
        A.jobs[2] = {p_vech, p_vecl, WH(OFF_WTRG), WL(OFF_WTRG), p_zb, p_T,  HH,     4, 0, 1536};
        A.jobs[3] = {p_vech, p_vecl, WH(OFF_WSRC), WL(OFF_WSRC), p_zb, p_S,  HH,     4, 0, 2048};
        gemm_kernel<<<148, 256, MG_SMEM, s2>>>(A);
    }
    cudaEventRecord(evB, s2);                       // ff/vp/T/S ready
    wdot_kernel<<<WDOT_GRID, 256, 0, s2>>>(src, dst, d_ij, out_df);
    cudaEventRecord(evC, s2);                       // branch done

    // ---- stream 0: critical chain ----
    // qkv (3 jobs, 192 tiles)
    {
        GArgs A{};
        A.njobs = 3; A.mode = 0; A.totalTiles = 192;
        A.jobs[0] = {p_xnh, p_xnl, WH(OFF_WQ), WL(OFF_WQ), p_zb, p_q,  HH, 4, 0, 0};
        A.jobs[1] = {p_xnh, p_xnl, WH(OFF_WK), WL(OFF_WK), p_zb, p_k,  HH, 4, 0, 64};
        A.jobs[2] = {p_xnh, p_xnl, WH(OFF_WV), WL(OFF_WV), p_zb, p_vv, HH, 4, 0, 128};
        gemm_kernel<<<192, 256, MG_SMEM>>>(A);
    }

    attn_kernel<<<64, 256>>>();

    // v = vatt @ Wao (64 tiles)
    {
        GArgs A{};
        A.njobs = 1; A.mode = 0; A.totalTiles = 64;
        A.jobs[0] = {p_vath, p_vatl, WH(OFF_WAO), WL(OFF_WAO), p_zb, p_v, HH, 4, 0, 0};
        gemm_kernel<<<64, 256, MG_SMEM>>>(A);
    }

    // vj (512 tiles, mode 1)
    {
        GArgs A{};
        A.njobs = 1; A.mode = 1; A.totalTiles = 512;
        A.jobs[0] = {p_fijh, p_fijl, WH(OFF_WDV), WL(OFF_WDV), bdv, nullptr, HH, 4, 0, 0};
        A.vsrc = p_v; A.srcidx = src; A.rij = r_ij; A.Oh = p_vjh; A.Ol = p_vjl;
        gemm_kernel<<<512, 256, MG_SMEM>>>(A);
    }

    // s12 (1024 tiles)
    {
        GArgs A{};
        A.njobs = 1; A.mode = 0; A.totalTiles = 1024;
        A.jobs[0] = {p_vjh, p_vjl, WH(OFF_WS), WL(OFF_WS), bs, p_s12, 2 * HH, 8, 1, 0};
        gemm_kernel<<<1024, 256, MG_SMEM>>>(A);
    }

    // gather (needs CSR)
    cudaStreamWaitEvent(0, evCSR, 0);
    gather_kernel<<<BN, 256>>>(p_s12, vec, d_ij, src, out_dvec);

    // o = x_agg @ Wo + bo (192 tiles)
    {
        GArgs A{};
        A.njobs = 1; A.mode = 0; A.totalTiles = 192;
        A.jobs[0] = {p_xagh, p_xagl, WH(OFF_WO), WL(OFF_WO), bo, p_o, 3 * HH, 12, 0, 0};
        gemm_kernel<<<192, 256, MG_SMEM>>>(A);
    }

    // finalize needs vp from s2 branch
    cudaStreamWaitEvent(0, evB, 0);
    finalize_kernel<<<BN, 256>>>(out_dx, out_dvec);

    // join branch (wdot) before returning
    cudaStreamWaitEvent(0, evC, 0);
}